// round 3
// baseline (speedup 1.0000x reference)
#include <cuda_runtime.h>
#include <math.h>

#define BATCH 2
#define SEQ 2048
#define DM 1024
#define NH 16
#define HD 64

// ---------------- scratch (static device globals; no allocs allowed) ----------------
__device__ float g_Q[(size_t)BATCH * NH * SEQ * HD];     // [b][h][s][hd], rope'd, 16MB
__device__ float g_K[(size_t)BATCH * NH * SEQ * HD];
__device__ float g_V[(size_t)BATCH * NH * SEQ * HD];
__device__ float g_Ctx[(size_t)BATCH * SEQ * DM];        // attention output, concat layout
__device__ float g_cos[SEQ * (HD / 2)];
__device__ float g_sin[SEQ * (HD / 2)];

// ---------------- RoPE table ----------------
__global__ void rope_table_kernel() {
    int idx = blockIdx.x * blockDim.x + threadIdx.x;
    if (idx >= SEQ * (HD / 2)) return;
    int s = idx >> 5;          // HD/2 = 32
    int p = idx & 31;
    float freq = powf(10000.0f, -(float)(2 * p) / (float)HD);
    float ang = (float)s * freq;
    g_cos[idx] = cosf(ang);
    g_sin[idx] = sinf(ang);
}

// ---------------- GEMM: C = A(MxK) @ B(NxK)^T ----------------
// MODE 0: plain row-major store C[M][N]
// MODE 1: RoPE + scatter into [b][h][s][hd]
// MODE 2: scatter into [b][h][s][hd] (no RoPE, for V)
template <int MODE>
__global__ void __launch_bounds__(256) gemm_kernel(const float* __restrict__ A,
                                                   const float* __restrict__ B,
                                                   float* __restrict__ C,
                                                   int M, int N, int K)
{
    __shared__ float As[16][132];   // transposed tiles: As[k][m]
    __shared__ float Bs[16][132];   // Bs[k][n]

    const int tid = threadIdx.x;
    const int ty = tid >> 4;        // 0..15
    const int tx = tid & 15;        // 0..15
    const int bm = blockIdx.y * 128;
    const int bn = blockIdx.x * 128;

    float acc[8][8];
#pragma unroll
    for (int i = 0; i < 8; i++)
#pragma unroll
        for (int j = 0; j < 8; j++) acc[i][j] = 0.0f;

    for (int k0 = 0; k0 < K; k0 += 16) {
#pragma unroll
        for (int t = tid; t < 512; t += 256) {
            const int row = t >> 2;
            const int kq = (t & 3) << 2;
            float4 va = *(const float4*)(A + (size_t)(bm + row) * K + k0 + kq);
            As[kq + 0][row] = va.x; As[kq + 1][row] = va.y;
            As[kq + 2][row] = va.z; As[kq + 3][row] = va.w;
            float4 vb = *(const float4*)(B + (size_t)(bn + row) * K + k0 + kq);
            Bs[kq + 0][row] = vb.x; Bs[kq + 1][row] = vb.y;
            Bs[kq + 2][row] = vb.z; Bs[kq + 3][row] = vb.w;
        }
        __syncthreads();

#pragma unroll
        for (int kk = 0; kk < 16; kk++) {
            float a[8], bv[8];
            *(float4*)&a[0]  = *(const float4*)&As[kk][ty * 8];
            *(float4*)&a[4]  = *(const float4*)&As[kk][ty * 8 + 4];
            *(float4*)&bv[0] = *(const float4*)&Bs[kk][tx * 8];
            *(float4*)&bv[4] = *(const float4*)&Bs[kk][tx * 8 + 4];
#pragma unroll
            for (int i = 0; i < 8; i++)
#pragma unroll
                for (int j = 0; j < 8; j++)
                    acc[i][j] = fmaf(a[i], bv[j], acc[i][j]);
        }
        __syncthreads();
    }

    const int row0 = bm + ty * 8;
    const int col0 = bn + tx * 8;

    if (MODE == 0) {
#pragma unroll
        for (int i = 0; i < 8; i++) {
            *(float4*)(C + (size_t)(row0 + i) * N + col0)     = *(float4*)&acc[i][0];
            *(float4*)(C + (size_t)(row0 + i) * N + col0 + 4) = *(float4*)&acc[i][4];
        }
    } else {
#pragma unroll
        for (int i = 0; i < 8; i++) {
            const int m = row0 + i;
            const int b = m >> 11;           // SEQ = 2048
            const int s = m & (SEQ - 1);
#pragma unroll
            for (int j = 0; j < 8; j += 2) {
                const int col = col0 + j;
                const int h = col >> 6;
                const int d0 = col & 63;
                float e = acc[i][j];
                float o = acc[i][j + 1];
                if (MODE == 1) {
                    const int p = d0 >> 1;
                    const float cs = g_cos[s * 32 + p];
                    const float sn = g_sin[s * 32 + p];
                    const float re = e * cs - o * sn;
                    const float ro = e * sn + o * cs;
                    e = re; o = ro;
                }
                const size_t idx = (((size_t)b * NH + h) * SEQ + s) * HD + d0;
                C[idx]     = e;
                C[idx + 1] = o;
            }
        }
    }
}

// ---------------- flash-style causal attention (fp32) ----------------
// grid: (SEQ/64, BATCH*NH), block 256. Each block: 64 queries, loops key tiles of 64.
__global__ void __launch_bounds__(256) attn_kernel()
{
    const int qb = blockIdx.x;
    const int bh = blockIdx.y;
    const int b  = bh >> 4;
    const int h  = bh & 15;
    const size_t base = (size_t)bh * SEQ * HD;

    extern __shared__ float smem[];
    float (*Qs)[68] = (float (*)[68])smem;
    float (*Ks)[68] = Qs + 64;
    float (*Vs)[68] = Ks + 64;
    float (*Ps)[68] = Vs + 64;

    const int tid = threadIdx.x;
    const int ty = tid >> 4;
    const int tx = tid & 15;

    // load Q tile (pre-scaled by 1/sqrt(hd) = 0.125)
#pragma unroll
    for (int t = tid; t < 1024; t += 256) {
        const int r = t >> 4;
        const int c = (t & 15) << 2;
        float4 v = *(const float4*)(g_Q + base + (size_t)(qb * 64 + r) * HD + c);
        Qs[r][c + 0] = v.x * 0.125f; Qs[r][c + 1] = v.y * 0.125f;
        Qs[r][c + 2] = v.z * 0.125f; Qs[r][c + 3] = v.w * 0.125f;
    }

    float m_i[4], l_i[4], o[4][4];
#pragma unroll
    for (int i = 0; i < 4; i++) {
        m_i[i] = -1e30f;
        l_i[i] = 0.0f;
#pragma unroll
        for (int j = 0; j < 4; j++) o[i][j] = 0.0f;
    }
    __syncthreads();

    for (int jb = 0; jb <= qb; jb++) {
        // load K,V tiles
#pragma unroll
        for (int t = tid; t < 1024; t += 256) {
            const int r = t >> 4;
            const int c = (t & 15) << 2;
            const size_t off = base + (size_t)(jb * 64 + r) * HD + c;
            *(float4*)&Ks[r][c] = *(const float4*)(g_K + off);
            *(float4*)&Vs[r][c] = *(const float4*)(g_V + off);
        }
        __syncthreads();

        // scores: S = Qs @ Ks^T  (thread tile 4x4)
        float sv[4][4];
#pragma unroll
        for (int i = 0; i < 4; i++)
#pragma unroll
            for (int j = 0; j < 4; j++) sv[i][j] = 0.0f;

#pragma unroll
        for (int d = 0; d < HD; d += 4) {
            float4 qa[4], kb[4];
#pragma unroll
            for (int i = 0; i < 4; i++) qa[i] = *(const float4*)&Qs[(ty << 2) + i][d];
#pragma unroll
            for (int j = 0; j < 4; j++) kb[j] = *(const float4*)&Ks[(tx << 2) + j][d];
#pragma unroll
            for (int i = 0; i < 4; i++)
#pragma unroll
                for (int j = 0; j < 4; j++) {
                    sv[i][j] = fmaf(qa[i].x, kb[j].x, sv[i][j]);
                    sv[i][j] = fmaf(qa[i].y, kb[j].y, sv[i][j]);
                    sv[i][j] = fmaf(qa[i].z, kb[j].z, sv[i][j]);
                    sv[i][j] = fmaf(qa[i].w, kb[j].w, sv[i][j]);
                }
        }

        // causal mask: only on the diagonal tile
        if (jb == qb) {
#pragma unroll
            for (int i = 0; i < 4; i++)
#pragma unroll
                for (int j = 0; j < 4; j++) {
                    const int q = (ty << 2) + i;
                    const int k = (tx << 2) + j;
                    if (k > q) sv[i][j] = -1e30f;
                }
        }

        // online softmax per row (reduce across 16 tx lanes)
#pragma unroll
        for (int i = 0; i < 4; i++) {
            float mt = fmaxf(fmaxf(sv[i][0], sv[i][1]), fmaxf(sv[i][2], sv[i][3]));
            mt = fmaxf(mt, __shfl_xor_sync(0xffffffffu, mt, 8));
            mt = fmaxf(mt, __shfl_xor_sync(0xffffffffu, mt, 4));
            mt = fmaxf(mt, __shfl_xor_sync(0xffffffffu, mt, 2));
            mt = fmaxf(mt, __shfl_xor_sync(0xffffffffu, mt, 1));
            const float m_new = fmaxf(m_i[i], mt);
            float ls = 0.0f;
#pragma unroll
            for (int j = 0; j < 4; j++) {
                sv[i][j] = __expf(sv[i][j] - m_new);
                ls += sv[i][j];
            }
            ls += __shfl_xor_sync(0xffffffffu, ls, 8);
            ls += __shfl_xor_sync(0xffffffffu, ls, 4);
            ls += __shfl_xor_sync(0xffffffffu, ls, 2);
            ls += __shfl_xor_sync(0xffffffffu, ls, 1);
            const float alpha = __expf(m_i[i] - m_new);
            l_i[i] = l_i[i] * alpha + ls;
            m_i[i] = m_new;
#pragma unroll
            for (int j = 0; j < 4; j++) o[i][j] *= alpha;
            *(float4*)&Ps[(ty << 2) + i][tx << 2] = *(float4*)&sv[i][0];
        }
        __syncthreads();

        // O += P @ V
#pragma unroll 4
        for (int k = 0; k < 64; k++) {
            const float a0 = Ps[(ty << 2) + 0][k];
            const float a1 = Ps[(ty << 2) + 1][k];
            const float a2 = Ps[(ty << 2) + 2][k];
            const float a3 = Ps[(ty << 2) + 3][k];
            const float4 v = *(const float4*)&Vs[k][tx << 2];
            o[0][0] = fmaf(a0, v.x, o[0][0]); o[0][1] = fmaf(a0, v.y, o[0][1]);
            o[0][2] = fmaf(a0, v.z, o[0][2]); o[0][3] = fmaf(a0, v.w, o[0][3]);
            o[1][0] = fmaf(a1, v.x, o[1][0]); o[1][1] = fmaf(a1, v.y, o[1][1]);
            o[1][2] = fmaf(a1, v.z, o[1][2]); o[1][3] = fmaf(a1, v.w, o[1][3]);
            o[2][0] = fmaf(a2, v.x, o[2][0]); o[2][1] = fmaf(a2, v.y, o[2][1]);
            o[2][2] = fmaf(a2, v.z, o[2][2]); o[2][3] = fmaf(a2, v.w, o[2][3]);
            o[3][0] = fmaf(a3, v.x, o[3][0]); o[3][1] = fmaf(a3, v.y, o[3][1]);
            o[3][2] = fmaf(a3, v.z, o[3][2]); o[3][3] = fmaf(a3, v.w, o[3][3]);
        }
        __syncthreads();
    }

    // epilogue: normalize + scatter to concat [b][s][d]
#pragma unroll
    for (int i = 0; i < 4; i++) {
        const float inv = 1.0f / l_i[i];
        const int sq = qb * 64 + (ty << 2) + i;
        float4 r;
        r.x = o[i][0] * inv; r.y = o[i][1] * inv;
        r.z = o[i][2] * inv; r.w = o[i][3] * inv;
        *(float4*)(g_Ctx + ((size_t)b * SEQ + sq) * DM + h * HD + (tx << 2)) = r;
    }
}

// ---------------- launch ----------------
extern "C" void kernel_launch(void* const* d_in, const int* in_sizes, int n_in,
                              void* d_out, int out_size)
{
    const float* x  = (const float*)d_in[0];
    const float* Wq = (const float*)d_in[1];
    const float* Wk = (const float*)d_in[2];
    const float* Wv = (const float*)d_in[3];
    const float* Wo = (const float*)d_in[4];
    float* out = (float*)d_out;

    float *pQ, *pK, *pV, *pCtx;
    cudaGetSymbolAddress((void**)&pQ,   g_Q);
    cudaGetSymbolAddress((void**)&pK,   g_K);
    cudaGetSymbolAddress((void**)&pV,   g_V);
    cudaGetSymbolAddress((void**)&pCtx, g_Ctx);

    const int M = BATCH * SEQ;   // 4096
    const int N = DM;            // 1024
    const int K = DM;            // 1024

    rope_table_kernel<<<(SEQ * 32 + 255) / 256, 256>>>();

    dim3 ggrid(N / 128, M / 128);
    gemm_kernel<1><<<ggrid, 256>>>(x, Wq, pQ, M, N, K);   // Q + RoPE
    gemm_kernel<1><<<ggrid, 256>>>(x, Wk, pK, M, N, K);   // K + RoPE
    gemm_kernel<2><<<ggrid, 256>>>(x, Wv, pV, M, N, K);   // V

    const int smem = 4 * 64 * 68 * (int)sizeof(float);    // 69632 B
    cudaFuncSetAttribute(attn_kernel, cudaFuncAttributeMaxDynamicSharedMemorySize, smem);
    attn_kernel<<<dim3(SEQ / 64, BATCH * NH), 256, smem>>>();

    gemm_kernel<0><<<ggrid, 256>>>(pCtx, Wo, out, M, N, K);
}

// round 6
// speedup vs baseline: 1.3067x; 1.3067x over previous
#include <cuda_runtime.h>
#include <cuda_bf16.h>
#include <math.h>
#include <stdint.h>

#define BATCH 2
#define SEQ 2048
#define DM 1024
#define NH 16
#define HD 64

// ---------------- scratch (static device globals; no allocs allowed) ----------------
__device__ float g_Q[(size_t)BATCH * NH * SEQ * HD];     // [b][h][s][hd], rope'd
__device__ float g_K[(size_t)BATCH * NH * SEQ * HD];
__device__ float g_V[(size_t)BATCH * NH * SEQ * HD];
__device__ float g_Ctx[(size_t)BATCH * SEQ * DM];        // attention output, concat layout
__device__ float g_cos[SEQ * (HD / 2)];
__device__ float g_sin[SEQ * (HD / 2)];

// split-bf16 operand buffers
__device__ __nv_bfloat16 g_Ah[(size_t)BATCH * SEQ * DM]; // activation hi (x, later Ctx)
__device__ __nv_bfloat16 g_Al[(size_t)BATCH * SEQ * DM]; // activation lo
__device__ __nv_bfloat16 g_Wh[4][(size_t)DM * DM];       // weights hi: q,k,v,o
__device__ __nv_bfloat16 g_Wl[4][(size_t)DM * DM];       // weights lo

// ---------------- PTX helpers (generic-PTX-safe: no tcgen05) ----------------
__device__ __forceinline__ uint32_t smem_u32(const void* p) {
    uint32_t a;
    asm("{ .reg .u64 t; cvta.to.shared.u64 t, %1; cvt.u32.u64 %0, t; }" : "=r"(a) : "l"(p));
    return a;
}

__device__ __forceinline__ void sts128(uint32_t addr, uint4 v) {
    asm volatile("st.shared.v4.b32 [%0], {%1,%2,%3,%4};"
                 :: "r"(addr), "r"(v.x), "r"(v.y), "r"(v.z), "r"(v.w) : "memory");
}

__device__ __forceinline__ void ldsm4(uint32_t* r, uint32_t addr) {
    asm volatile("ldmatrix.sync.aligned.m8n8.x4.shared.b16 {%0,%1,%2,%3}, [%4];"
                 : "=r"(r[0]), "=r"(r[1]), "=r"(r[2]), "=r"(r[3]) : "r"(addr));
}

__device__ __forceinline__ void mma16816(float* c, const uint32_t* a, uint32_t b0, uint32_t b1) {
    asm volatile(
        "mma.sync.aligned.m16n8k16.row.col.f32.bf16.bf16.f32 "
        "{%0,%1,%2,%3}, {%4,%5,%6,%7}, {%8,%9}, {%0,%1,%2,%3};"
        : "+f"(c[0]), "+f"(c[1]), "+f"(c[2]), "+f"(c[3])
        : "r"(a[0]), "r"(a[1]), "r"(a[2]), "r"(a[3]), "r"(b0), "r"(b1));
}

// ---------------- RoPE table ----------------
__global__ void rope_table_kernel() {
    int idx = blockIdx.x * blockDim.x + threadIdx.x;
    if (idx >= SEQ * (HD / 2)) return;
    int s = idx >> 5;          // HD/2 = 32
    int p = idx & 31;
    float freq = powf(10000.0f, -(float)(2 * p) / (float)HD);
    float ang = (float)s * freq;
    g_cos[idx] = cosf(ang);
    g_sin[idx] = sinf(ang);
}

// ---------------- fp32 -> bf16 hi/lo split ----------------
__global__ void split_kernel(const float* __restrict__ x,
                             __nv_bfloat16* __restrict__ hi,
                             __nv_bfloat16* __restrict__ lo, int n4) {
    int i = blockIdx.x * blockDim.x + threadIdx.x;
    if (i >= n4) return;
    float4 v = ((const float4*)x)[i];
    __nv_bfloat16 h0 = __float2bfloat16(v.x);
    __nv_bfloat16 h1 = __float2bfloat16(v.y);
    __nv_bfloat16 h2 = __float2bfloat16(v.z);
    __nv_bfloat16 h3 = __float2bfloat16(v.w);
    __nv_bfloat16 l0 = __float2bfloat16(v.x - __bfloat162float(h0));
    __nv_bfloat16 l1 = __float2bfloat16(v.y - __bfloat162float(h1));
    __nv_bfloat16 l2 = __float2bfloat16(v.z - __bfloat162float(h2));
    __nv_bfloat16 l3 = __float2bfloat16(v.w - __bfloat162float(h3));
    __nv_bfloat162 H0; H0.x = h0; H0.y = h1;
    __nv_bfloat162 H1; H1.x = h2; H1.y = h3;
    __nv_bfloat162 L0; L0.x = l0; L0.y = l1;
    __nv_bfloat162 L1; L1.x = l2; L1.y = l3;
    ((__nv_bfloat162*)hi)[2 * i]     = H0;
    ((__nv_bfloat162*)hi)[2 * i + 1] = H1;
    ((__nv_bfloat162*)lo)[2 * i]     = L0;
    ((__nv_bfloat162*)lo)[2 * i + 1] = L1;
}

// ---------------- HMMA split-bf16 GEMM: C = A(MxK) @ B(NxK)^T ----------------
// M=4096, N=1024, K=1024. Block tile 128x128, 8 warps (4x2), warp tile 32x64,
// K-chunk 64. SW128 xor swizzle; plain ldmatrix for both A and B (both k-major).
// MODE 0: row-major C[M][N]
// MODE 1: RoPE + scatter into [b][h][s][hd]
// MODE 2: scatter into [b][h][s][hd] (no RoPE)
template <int MODE>
__global__ void __launch_bounds__(256) tgemm_kernel(const __nv_bfloat16* __restrict__ Ah,
                                                    const __nv_bfloat16* __restrict__ Al,
                                                    const __nv_bfloat16* __restrict__ Bh,
                                                    const __nv_bfloat16* __restrict__ Bl,
                                                    float* __restrict__ C)
{
    constexpr int Kdim = DM;
    extern __shared__ char smem[];
    const int tid = threadIdx.x;
    const int wid = tid >> 5;
    const int l   = tid & 31;
    const int bm = blockIdx.y * 128;
    const int bn = blockIdx.x * 128;

    const uint32_t tb  = (smem_u32(smem) + 127) & ~127u;
    const uint32_t sAh = tb;
    const uint32_t sAl = tb + 16384;
    const uint32_t sBh = tb + 32768;
    const uint32_t sBl = tb + 49152;

    const int wm = (wid >> 1) * 32;   // warp m offset within block tile
    const int wn = (wid & 1) * 64;    // warp n offset

    float acc[2][8][4];
#pragma unroll
    for (int mf = 0; mf < 2; mf++)
#pragma unroll
        for (int nf = 0; nf < 8; nf++)
#pragma unroll
            for (int q = 0; q < 4; q++) acc[mf][nf][q] = 0.0f;

    // ldmatrix lane addressing (same pattern for A and B, both k-major)
    const int frow = (l & 7) + ((l >> 3) & 1) * 8;  // row within 16-row frag
    const int koff = ((l >> 4) & 1) * 8;            // k-block offset within k-step

    for (int c = 0; c < Kdim / 64; c++) {
        const int k0 = c * 64;
#pragma unroll
        for (int i = 0; i < 4; i++) {
            const int id = tid + i * 256;
            const int row = id >> 3;
            const int ch = id & 7;
            const uint32_t off = row * 128 + ch * 16;
            const uint32_t sw = off ^ ((off >> 3) & 0x70);
            const size_t ga = (size_t)(bm + row) * Kdim + k0 + ch * 8;
            const size_t gb = (size_t)(bn + row) * Kdim + k0 + ch * 8;
            sts128(sAh + sw, *(const uint4*)(Ah + ga));
            sts128(sAl + sw, *(const uint4*)(Al + ga));
            sts128(sBh + sw, *(const uint4*)(Bh + gb));
            sts128(sBl + sw, *(const uint4*)(Bl + gb));
        }
        __syncthreads();

#pragma unroll
        for (int ks = 0; ks < 4; ks++) {
            const int kk = ks * 16 + koff;
            uint32_t ahf[2][4], alf[2][4];
#pragma unroll
            for (int mf = 0; mf < 2; mf++) {
                const uint32_t off = (uint32_t)(wm + mf * 16 + frow) * 128 + kk * 2;
                const uint32_t sw = off ^ ((off >> 3) & 0x70);
                ldsm4(ahf[mf], sAh + sw);
                ldsm4(alf[mf], sAl + sw);
            }
#pragma unroll
            for (int np = 0; np < 4; np++) {
                const uint32_t off = (uint32_t)(wn + np * 16 + frow) * 128 + kk * 2;
                const uint32_t sw = off ^ ((off >> 3) & 0x70);
                uint32_t bhf[4], blf[4];
                ldsm4(bhf, sBh + sw);
                ldsm4(blf, sBl + sw);
                // x4 on B yields: r0 = nfrag0 k-lo, r1 = nfrag1 k-lo,
                //                 r2 = nfrag0 k-hi, r3 = nfrag1 k-hi
#pragma unroll
                for (int mf = 0; mf < 2; mf++) {
                    mma16816(acc[mf][np * 2 + 0], ahf[mf], bhf[0], bhf[2]);
                    mma16816(acc[mf][np * 2 + 0], ahf[mf], blf[0], blf[2]);
                    mma16816(acc[mf][np * 2 + 0], alf[mf], bhf[0], bhf[2]);
                    mma16816(acc[mf][np * 2 + 1], ahf[mf], bhf[1], bhf[3]);
                    mma16816(acc[mf][np * 2 + 1], ahf[mf], blf[1], blf[3]);
                    mma16816(acc[mf][np * 2 + 1], alf[mf], bhf[1], bhf[3]);
                }
            }
        }
        __syncthreads();
    }

    // epilogue: acc thread layout: rows (l>>2)+{0,8}, cols (l&3)*2 + {0,1}
    const int r_lane = l >> 2;
    const int c_lane = (l & 3) * 2;
#pragma unroll
    for (int mf = 0; mf < 2; mf++) {
#pragma unroll
        for (int half = 0; half < 2; half++) {
            const int mrow = bm + wm + mf * 16 + r_lane + half * 8;
            const int b = mrow >> 11;            // SEQ = 2048
            const int s = mrow & (SEQ - 1);
#pragma unroll
            for (int nf = 0; nf < 8; nf++) {
                float e = acc[mf][nf][half * 2 + 0];
                float o = acc[mf][nf][half * 2 + 1];
                const int col = bn + wn + nf * 8 + c_lane;   // even
                if (MODE == 0) {
                    float2 v; v.x = e; v.y = o;
                    *(float2*)(C + (size_t)mrow * DM + col) = v;
                } else {
                    const int h = col >> 6;
                    const int d0 = col & 63;
                    if (MODE == 1) {
                        const int p = d0 >> 1;
                        const float cs = g_cos[s * 32 + p];
                        const float sn = g_sin[s * 32 + p];
                        const float re = e * cs - o * sn;
                        const float ro = e * sn + o * cs;
                        e = re; o = ro;
                    }
                    float2 v; v.x = e; v.y = o;
                    *(float2*)(C + (((size_t)b * NH + h) * SEQ + s) * HD + d0) = v;
                }
            }
        }
    }
}

// ---------------- flash-style causal attention (fp32, unchanged) ----------------
__global__ void __launch_bounds__(256) attn_kernel()
{
    const int qb = blockIdx.x;
    const int bh = blockIdx.y;
    const int b  = bh >> 4;
    const int h  = bh & 15;
    const size_t base = (size_t)bh * SEQ * HD;

    extern __shared__ float fsm[];
    float (*Qs)[68] = (float (*)[68])fsm;
    float (*Ks)[68] = Qs + 64;
    float (*Vs)[68] = Ks + 64;
    float (*Ps)[68] = Vs + 64;

    const int tid = threadIdx.x;
    const int ty = tid >> 4;
    const int tx = tid & 15;

#pragma unroll
    for (int t = tid; t < 1024; t += 256) {
        const int r = t >> 4;
        const int c = (t & 15) << 2;
        float4 v = *(const float4*)(g_Q + base + (size_t)(qb * 64 + r) * HD + c);
        Qs[r][c + 0] = v.x * 0.125f; Qs[r][c + 1] = v.y * 0.125f;
        Qs[r][c + 2] = v.z * 0.125f; Qs[r][c + 3] = v.w * 0.125f;
    }

    float m_i[4], l_i[4], o[4][4];
#pragma unroll
    for (int i = 0; i < 4; i++) {
        m_i[i] = -1e30f;
        l_i[i] = 0.0f;
#pragma unroll
        for (int j = 0; j < 4; j++) o[i][j] = 0.0f;
    }
    __syncthreads();

    for (int jb = 0; jb <= qb; jb++) {
#pragma unroll
        for (int t = tid; t < 1024; t += 256) {
            const int r = t >> 4;
            const int c = (t & 15) << 2;
            const size_t off = base + (size_t)(jb * 64 + r) * HD + c;
            *(float4*)&Ks[r][c] = *(const float4*)(g_K + off);
            *(float4*)&Vs[r][c] = *(const float4*)(g_V + off);
        }
        __syncthreads();

        float sv[4][4];
#pragma unroll
        for (int i = 0; i < 4; i++)
#pragma unroll
            for (int j = 0; j < 4; j++) sv[i][j] = 0.0f;

#pragma unroll
        for (int d = 0; d < HD; d += 4) {
            float4 qa[4], kb[4];
#pragma unroll
            for (int i = 0; i < 4; i++) qa[i] = *(const float4*)&Qs[(ty << 2) + i][d];
#pragma unroll
            for (int j = 0; j < 4; j++) kb[j] = *(const float4*)&Ks[(tx << 2) + j][d];
#pragma unroll
            for (int i = 0; i < 4; i++)
#pragma unroll
                for (int j = 0; j < 4; j++) {
                    sv[i][j] = fmaf(qa[i].x, kb[j].x, sv[i][j]);
                    sv[i][j] = fmaf(qa[i].y, kb[j].y, sv[i][j]);
                    sv[i][j] = fmaf(qa[i].z, kb[j].z, sv[i][j]);
                    sv[i][j] = fmaf(qa[i].w, kb[j].w, sv[i][j]);
                }
        }

        if (jb == qb) {
#pragma unroll
            for (int i = 0; i < 4; i++)
#pragma unroll
                for (int j = 0; j < 4; j++) {
                    const int q = (ty << 2) + i;
                    const int k = (tx << 2) + j;
                    if (k > q) sv[i][j] = -1e30f;
                }
        }

#pragma unroll
        for (int i = 0; i < 4; i++) {
            float mt = fmaxf(fmaxf(sv[i][0], sv[i][1]), fmaxf(sv[i][2], sv[i][3]));
            mt = fmaxf(mt, __shfl_xor_sync(0xffffffffu, mt, 8));
            mt = fmaxf(mt, __shfl_xor_sync(0xffffffffu, mt, 4));
            mt = fmaxf(mt, __shfl_xor_sync(0xffffffffu, mt, 2));
            mt = fmaxf(mt, __shfl_xor_sync(0xffffffffu, mt, 1));
            const float m_new = fmaxf(m_i[i], mt);
            float ls = 0.0f;
#pragma unroll
            for (int j = 0; j < 4; j++) {
                sv[i][j] = __expf(sv[i][j] - m_new);
                ls += sv[i][j];
            }
            ls += __shfl_xor_sync(0xffffffffu, ls, 8);
            ls += __shfl_xor_sync(0xffffffffu, ls, 4);
            ls += __shfl_xor_sync(0xffffffffu, ls, 2);
            ls += __shfl_xor_sync(0xffffffffu, ls, 1);
            const float alpha = __expf(m_i[i] - m_new);
            l_i[i] = l_i[i] * alpha + ls;
            m_i[i] = m_new;
#pragma unroll
            for (int j = 0; j < 4; j++) o[i][j] *= alpha;
            *(float4*)&Ps[(ty << 2) + i][tx << 2] = *(float4*)&sv[i][0];
        }
        __syncthreads();

#pragma unroll 4
        for (int k = 0; k < 64; k++) {
            const float a0 = Ps[(ty << 2) + 0][k];
            const float a1 = Ps[(ty << 2) + 1][k];
            const float a2 = Ps[(ty << 2) + 2][k];
            const float a3 = Ps[(ty << 2) + 3][k];
            const float4 v = *(const float4*)&Vs[k][tx << 2];
            o[0][0] = fmaf(a0, v.x, o[0][0]); o[0][1] = fmaf(a0, v.y, o[0][1]);
            o[0][2] = fmaf(a0, v.z, o[0][2]); o[0][3] = fmaf(a0, v.w, o[0][3]);
            o[1][0] = fmaf(a1, v.x, o[1][0]); o[1][1] = fmaf(a1, v.y, o[1][1]);
            o[1][2] = fmaf(a1, v.z, o[1][2]); o[1][3] = fmaf(a1, v.w, o[1][3]);
            o[2][0] = fmaf(a2, v.x, o[2][0]); o[2][1] = fmaf(a2, v.y, o[2][1]);
            o[2][2] = fmaf(a2, v.z, o[2][2]); o[2][3] = fmaf(a2, v.w, o[2][3]);
            o[3][0] = fmaf(a3, v.x, o[3][0]); o[3][1] = fmaf(a3, v.y, o[3][1]);
            o[3][2] = fmaf(a3, v.z, o[3][2]); o[3][3] = fmaf(a3, v.w, o[3][3]);
        }
        __syncthreads();
    }

#pragma unroll
    for (int i = 0; i < 4; i++) {
        const float inv = 1.0f / l_i[i];
        const int sq = qb * 64 + (ty << 2) + i;
        float4 r;
        r.x = o[i][0] * inv; r.y = o[i][1] * inv;
        r.z = o[i][2] * inv; r.w = o[i][3] * inv;
        *(float4*)(g_Ctx + ((size_t)b * SEQ + sq) * DM + h * HD + (tx << 2)) = r;
    }
}

// ---------------- launch ----------------
extern "C" void kernel_launch(void* const* d_in, const int* in_sizes, int n_in,
                              void* d_out, int out_size)
{
    const float* x  = (const float*)d_in[0];
    const float* Wq = (const float*)d_in[1];
    const float* Wk = (const float*)d_in[2];
    const float* Wv = (const float*)d_in[3];
    const float* Wo = (const float*)d_in[4];
    float* out = (float*)d_out;

    float *pQ, *pK, *pV, *pCtx;
    cudaGetSymbolAddress((void**)&pQ,   g_Q);
    cudaGetSymbolAddress((void**)&pK,   g_K);
    cudaGetSymbolAddress((void**)&pV,   g_V);
    cudaGetSymbolAddress((void**)&pCtx, g_Ctx);
    __nv_bfloat16 *pAh, *pAl, *pWh, *pWl;
    cudaGetSymbolAddress((void**)&pAh, g_Ah);
    cudaGetSymbolAddress((void**)&pAl, g_Al);
    cudaGetSymbolAddress((void**)&pWh, g_Wh);
    cudaGetSymbolAddress((void**)&pWl, g_Wl);

    const int GSMEM = 65536 + 256;
    cudaFuncSetAttribute(tgemm_kernel<0>, cudaFuncAttributeMaxDynamicSharedMemorySize, GSMEM);
    cudaFuncSetAttribute(tgemm_kernel<1>, cudaFuncAttributeMaxDynamicSharedMemorySize, GSMEM);
    cudaFuncSetAttribute(tgemm_kernel<2>, cudaFuncAttributeMaxDynamicSharedMemorySize, GSMEM);

    rope_table_kernel<<<(SEQ * 32 + 255) / 256, 256>>>();

    // split activations + weights into bf16 hi/lo
    const int nx4 = BATCH * SEQ * DM / 4;     // 1,048,576
    const int nw4 = DM * DM / 4;              // 262,144
    split_kernel<<<(nx4 + 255) / 256, 256>>>(x,  pAh, pAl, nx4);
    split_kernel<<<(nw4 + 255) / 256, 256>>>(Wq, pWh + 0 * (size_t)DM * DM, pWl + 0 * (size_t)DM * DM, nw4);
    split_kernel<<<(nw4 + 255) / 256, 256>>>(Wk, pWh + 1 * (size_t)DM * DM, pWl + 1 * (size_t)DM * DM, nw4);
    split_kernel<<<(nw4 + 255) / 256, 256>>>(Wv, pWh + 2 * (size_t)DM * DM, pWl + 2 * (size_t)DM * DM, nw4);
    split_kernel<<<(nw4 + 255) / 256, 256>>>(Wo, pWh + 3 * (size_t)DM * DM, pWl + 3 * (size_t)DM * DM, nw4);

    dim3 ggrid(DM / 128, BATCH * SEQ / 128);  // (8, 32)
    tgemm_kernel<1><<<ggrid, 256, GSMEM>>>(pAh, pAl, pWh + 0 * (size_t)DM * DM, pWl + 0 * (size_t)DM * DM, pQ);
    tgemm_kernel<1><<<ggrid, 256, GSMEM>>>(pAh, pAl, pWh + 1 * (size_t)DM * DM, pWl + 1 * (size_t)DM * DM, pK);
    tgemm_kernel<2><<<ggrid, 256, GSMEM>>>(pAh, pAl, pWh + 2 * (size_t)DM * DM, pWl + 2 * (size_t)DM * DM, pV);

    const int asmem = 4 * 64 * 68 * (int)sizeof(float);    // 69632 B
    cudaFuncSetAttribute(attn_kernel, cudaFuncAttributeMaxDynamicSharedMemorySize, asmem);
    attn_kernel<<<dim3(SEQ / 64, BATCH * NH), 256, asmem>>>();

    split_kernel<<<(nx4 + 255) / 256, 256>>>(pCtx, pAh, pAl, nx4);
    tgemm_kernel<0><<<ggrid, 256, GSMEM>>>(pAh, pAl, pWh + 3 * (size_t)DM * DM, pWl + 3 * (size_t)DM * DM, out);
}

// round 7
// speedup vs baseline: 2.7579x; 2.1105x over previous
#include <cuda_runtime.h>
#include <cuda_bf16.h>
#include <math.h>
#include <stdint.h>

#define BATCH 2
#define SEQ 2048
#define DM 1024
#define NH 16
#define HD 64

// ---------------- scratch (static device globals; no allocs allowed) ----------------
__device__ float g_Ctx[(size_t)BATCH * SEQ * DM];        // attention output, concat layout
__device__ float g_cos[SEQ * (HD / 2)];
__device__ float g_sin[SEQ * (HD / 2)];

// split-bf16 Q/K/V, [b][h][s][hd]
__device__ __nv_bfloat16 g_Qh[(size_t)BATCH * NH * SEQ * HD];
__device__ __nv_bfloat16 g_Ql[(size_t)BATCH * NH * SEQ * HD];
__device__ __nv_bfloat16 g_Kh[(size_t)BATCH * NH * SEQ * HD];
__device__ __nv_bfloat16 g_Kl[(size_t)BATCH * NH * SEQ * HD];
__device__ __nv_bfloat16 g_Vh[(size_t)BATCH * NH * SEQ * HD];
__device__ __nv_bfloat16 g_Vl[(size_t)BATCH * NH * SEQ * HD];

// split-bf16 GEMM operand buffers
__device__ __nv_bfloat16 g_Ah[(size_t)BATCH * SEQ * DM]; // activation hi (x, later Ctx)
__device__ __nv_bfloat16 g_Al[(size_t)BATCH * SEQ * DM]; // activation lo
__device__ __nv_bfloat16 g_Wh[4][(size_t)DM * DM];       // weights hi: q,k,v,o
__device__ __nv_bfloat16 g_Wl[4][(size_t)DM * DM];       // weights lo

// ---------------- PTX helpers (generic-PTX-safe: no tcgen05) ----------------
__device__ __forceinline__ uint32_t smem_u32(const void* p) {
    uint32_t a;
    asm("{ .reg .u64 t; cvta.to.shared.u64 t, %1; cvt.u32.u64 %0, t; }" : "=r"(a) : "l"(p));
    return a;
}

__device__ __forceinline__ void sts128(uint32_t addr, uint4 v) {
    asm volatile("st.shared.v4.b32 [%0], {%1,%2,%3,%4};"
                 :: "r"(addr), "r"(v.x), "r"(v.y), "r"(v.z), "r"(v.w) : "memory");
}

__device__ __forceinline__ void ldsm4(uint32_t* r, uint32_t addr) {
    asm volatile("ldmatrix.sync.aligned.m8n8.x4.shared.b16 {%0,%1,%2,%3}, [%4];"
                 : "=r"(r[0]), "=r"(r[1]), "=r"(r[2]), "=r"(r[3]) : "r"(addr));
}

__device__ __forceinline__ void ldsm4t(uint32_t* r, uint32_t addr) {
    asm volatile("ldmatrix.sync.aligned.m8n8.x4.trans.shared.b16 {%0,%1,%2,%3}, [%4];"
                 : "=r"(r[0]), "=r"(r[1]), "=r"(r[2]), "=r"(r[3]) : "r"(addr));
}

__device__ __forceinline__ void mma16816(float* c, const uint32_t* a, uint32_t b0, uint32_t b1) {
    asm volatile(
        "mma.sync.aligned.m16n8k16.row.col.f32.bf16.bf16.f32 "
        "{%0,%1,%2,%3}, {%4,%5,%6,%7}, {%8,%9}, {%0,%1,%2,%3};"
        : "+f"(c[0]), "+f"(c[1]), "+f"(c[2]), "+f"(c[3])
        : "r"(a[0]), "r"(a[1]), "r"(a[2]), "r"(a[3]), "r"(b0), "r"(b1));
}

// split two fp32 -> packed bf16x2 hi + bf16x2 lo (element0 in low half)
__device__ __forceinline__ void split_pack(float a, float b, uint32_t& hi, uint32_t& lo) {
    __nv_bfloat16 ha = __float2bfloat16(a), hb = __float2bfloat16(b);
    __nv_bfloat16 la = __float2bfloat16(a - __bfloat162float(ha));
    __nv_bfloat16 lb = __float2bfloat16(b - __bfloat162float(hb));
    __nv_bfloat162 H; H.x = ha; H.y = hb;
    __nv_bfloat162 L; L.x = la; L.y = lb;
    hi = *(uint32_t*)&H;
    lo = *(uint32_t*)&L;
}

// ---------------- RoPE table ----------------
__global__ void rope_table_kernel() {
    int idx = blockIdx.x * blockDim.x + threadIdx.x;
    if (idx >= SEQ * (HD / 2)) return;
    int s = idx >> 5;          // HD/2 = 32
    int p = idx & 31;
    float freq = powf(10000.0f, -(float)(2 * p) / (float)HD);
    float ang = (float)s * freq;
    g_cos[idx] = cosf(ang);
    g_sin[idx] = sinf(ang);
}

// ---------------- fp32 -> bf16 hi/lo split ----------------
__global__ void split_kernel(const float* __restrict__ x,
                             __nv_bfloat16* __restrict__ hi,
                             __nv_bfloat16* __restrict__ lo, int n4) {
    int i = blockIdx.x * blockDim.x + threadIdx.x;
    if (i >= n4) return;
    float4 v = ((const float4*)x)[i];
    __nv_bfloat16 h0 = __float2bfloat16(v.x);
    __nv_bfloat16 h1 = __float2bfloat16(v.y);
    __nv_bfloat16 h2 = __float2bfloat16(v.z);
    __nv_bfloat16 h3 = __float2bfloat16(v.w);
    __nv_bfloat16 l0 = __float2bfloat16(v.x - __bfloat162float(h0));
    __nv_bfloat16 l1 = __float2bfloat16(v.y - __bfloat162float(h1));
    __nv_bfloat16 l2 = __float2bfloat16(v.z - __bfloat162float(h2));
    __nv_bfloat16 l3 = __float2bfloat16(v.w - __bfloat162float(h3));
    __nv_bfloat162 H0; H0.x = h0; H0.y = h1;
    __nv_bfloat162 H1; H1.x = h2; H1.y = h3;
    __nv_bfloat162 L0; L0.x = l0; L0.y = l1;
    __nv_bfloat162 L1; L1.x = l2; L1.y = l3;
    ((__nv_bfloat162*)hi)[2 * i]     = H0;
    ((__nv_bfloat162*)hi)[2 * i + 1] = H1;
    ((__nv_bfloat162*)lo)[2 * i]     = L0;
    ((__nv_bfloat162*)lo)[2 * i + 1] = L1;
}

// ---------------- HMMA split-bf16 GEMM: C = A(MxK) @ B(NxK)^T ----------------
// MODE 0: row-major fp32 C[M][N]
// MODE 1: RoPE, then split-bf16 scatter into Ch/Cl [b][h][s][hd]
// MODE 2: split-bf16 scatter into Ch/Cl (no RoPE)
template <int MODE>
__global__ void __launch_bounds__(256) tgemm_kernel(const __nv_bfloat16* __restrict__ Ah,
                                                    const __nv_bfloat16* __restrict__ Al,
                                                    const __nv_bfloat16* __restrict__ Bh,
                                                    const __nv_bfloat16* __restrict__ Bl,
                                                    float* __restrict__ C,
                                                    __nv_bfloat16* __restrict__ Ch,
                                                    __nv_bfloat16* __restrict__ Cl)
{
    constexpr int Kdim = DM;
    extern __shared__ char smem[];
    const int tid = threadIdx.x;
    const int wid = tid >> 5;
    const int l   = tid & 31;
    const int bm = blockIdx.y * 128;
    const int bn = blockIdx.x * 128;

    const uint32_t tb  = (smem_u32(smem) + 127) & ~127u;
    const uint32_t sAh = tb;
    const uint32_t sAl = tb + 16384;
    const uint32_t sBh = tb + 32768;
    const uint32_t sBl = tb + 49152;

    const int wm = (wid >> 1) * 32;
    const int wn = (wid & 1) * 64;

    float acc[2][8][4];
#pragma unroll
    for (int mf = 0; mf < 2; mf++)
#pragma unroll
        for (int nf = 0; nf < 8; nf++)
#pragma unroll
            for (int q = 0; q < 4; q++) acc[mf][nf][q] = 0.0f;

    const int frow = (l & 7) + ((l >> 3) & 1) * 8;
    const int koff = ((l >> 4) & 1) * 8;

    for (int c = 0; c < Kdim / 64; c++) {
        const int k0 = c * 64;
#pragma unroll
        for (int i = 0; i < 4; i++) {
            const int id = tid + i * 256;
            const int row = id >> 3;
            const int ch = id & 7;
            const uint32_t off = row * 128 + ch * 16;
            const uint32_t sw = off ^ ((off >> 3) & 0x70);
            const size_t ga = (size_t)(bm + row) * Kdim + k0 + ch * 8;
            const size_t gb = (size_t)(bn + row) * Kdim + k0 + ch * 8;
            sts128(sAh + sw, *(const uint4*)(Ah + ga));
            sts128(sAl + sw, *(const uint4*)(Al + ga));
            sts128(sBh + sw, *(const uint4*)(Bh + gb));
            sts128(sBl + sw, *(const uint4*)(Bl + gb));
        }
        __syncthreads();

#pragma unroll
        for (int ks = 0; ks < 4; ks++) {
            const int kk = ks * 16 + koff;
            uint32_t ahf[2][4], alf[2][4];
#pragma unroll
            for (int mf = 0; mf < 2; mf++) {
                const uint32_t off = (uint32_t)(wm + mf * 16 + frow) * 128 + kk * 2;
                const uint32_t sw = off ^ ((off >> 3) & 0x70);
                ldsm4(ahf[mf], sAh + sw);
                ldsm4(alf[mf], sAl + sw);
            }
#pragma unroll
            for (int np = 0; np < 4; np++) {
                const uint32_t off = (uint32_t)(wn + np * 16 + frow) * 128 + kk * 2;
                const uint32_t sw = off ^ ((off >> 3) & 0x70);
                uint32_t bhf[4], blf[4];
                ldsm4(bhf, sBh + sw);
                ldsm4(blf, sBl + sw);
#pragma unroll
                for (int mf = 0; mf < 2; mf++) {
                    mma16816(acc[mf][np * 2 + 0], ahf[mf], bhf[0], bhf[2]);
                    mma16816(acc[mf][np * 2 + 0], ahf[mf], blf[0], blf[2]);
                    mma16816(acc[mf][np * 2 + 0], alf[mf], bhf[0], bhf[2]);
                    mma16816(acc[mf][np * 2 + 1], ahf[mf], bhf[1], bhf[3]);
                    mma16816(acc[mf][np * 2 + 1], ahf[mf], blf[1], blf[3]);
                    mma16816(acc[mf][np * 2 + 1], alf[mf], bhf[1], bhf[3]);
                }
            }
        }
        __syncthreads();
    }

    const int r_lane = l >> 2;
    const int c_lane = (l & 3) * 2;
#pragma unroll
    for (int mf = 0; mf < 2; mf++) {
#pragma unroll
        for (int half = 0; half < 2; half++) {
            const int mrow = bm + wm + mf * 16 + r_lane + half * 8;
            const int b = mrow >> 11;            // SEQ = 2048
            const int s = mrow & (SEQ - 1);
#pragma unroll
            for (int nf = 0; nf < 8; nf++) {
                float e = acc[mf][nf][half * 2 + 0];
                float o = acc[mf][nf][half * 2 + 1];
                const int col = bn + wn + nf * 8 + c_lane;   // even
                if (MODE == 0) {
                    float2 v; v.x = e; v.y = o;
                    *(float2*)(C + (size_t)mrow * DM + col) = v;
                } else {
                    const int h = col >> 6;
                    const int d0 = col & 63;
                    if (MODE == 1) {
                        const int p = d0 >> 1;
                        const float cs = g_cos[s * 32 + p];
                        const float sn = g_sin[s * 32 + p];
                        const float re = e * cs - o * sn;
                        const float ro = e * sn + o * cs;
                        e = re; o = ro;
                    }
                    const size_t idx = (((size_t)b * NH + h) * SEQ + s) * HD + d0;
                    uint32_t hi, lo;
                    split_pack(e, o, hi, lo);
                    *(uint32_t*)(Ch + idx) = hi;
                    *(uint32_t*)(Cl + idx) = lo;
                }
            }
        }
    }
}

// ---------------- HMMA flash attention (split-bf16, causal) ----------------
// grid (SEQ/64, BATCH*NH), 128 threads = 4 warps x 16 query rows.
__global__ void __launch_bounds__(128) attn_hmma_kernel()
{
    const int qb = blockIdx.x;
    const int bh = blockIdx.y;
    const int b  = bh >> 4;
    const int h  = bh & 15;
    const size_t base = (size_t)bh * SEQ * HD;

    extern __shared__ char smem[];
    const uint32_t tb  = (smem_u32(smem) + 127) & ~127u;
    const uint32_t sQh = tb;
    const uint32_t sQl = tb + 8192;
    const uint32_t sKh = tb + 16384;
    const uint32_t sKl = tb + 24576;
    const uint32_t sVh = tb + 32768;
    const uint32_t sVl = tb + 40960;

    const int tid = threadIdx.x;
    const int wid = tid >> 5;
    const int l   = tid & 31;
    const int wm  = wid * 16;                       // warp's query-row offset
    const int frow = (l & 7) + ((l >> 3) & 1) * 8;
    const int koff = ((l >> 4) & 1) * 8;
    const int r  = l >> 2;
    const int cj = (l & 3) * 2;

    // load Q tile (64 x 64 bf16, hi+lo) swizzled
#pragma unroll
    for (int i = 0; i < 4; i++) {
        const int id = tid + i * 128;
        const int row = id >> 3;
        const int ch = id & 7;
        const uint32_t off = row * 128 + ch * 16;
        const uint32_t sw = off ^ ((off >> 3) & 0x70);
        const size_t g = base + (size_t)(qb * 64 + row) * HD + ch * 8;
        sts128(sQh + sw, *(const uint4*)(g_Qh + g));
        sts128(sQl + sw, *(const uint4*)(g_Ql + g));
    }
    __syncthreads();

    // preload Q fragments (16 rows x 64 k)
    uint32_t qh[4][4], ql[4][4];
#pragma unroll
    for (int ks = 0; ks < 4; ks++) {
        const uint32_t off = (uint32_t)(wm + frow) * 128 + (ks * 16 + koff) * 2;
        const uint32_t sw = off ^ ((off >> 3) & 0x70);
        ldsm4(qh[ks], sQh + sw);
        ldsm4(ql[ks], sQl + sw);
    }

    float m0 = -1e30f, m1 = -1e30f, l0 = 0.0f, l1 = 0.0f;
    float o[8][4];
#pragma unroll
    for (int nf = 0; nf < 8; nf++)
#pragma unroll
        for (int q = 0; q < 4; q++) o[nf][q] = 0.0f;

    for (int jb = 0; jb <= qb; jb++) {
        // load K,V tiles (hi+lo)
#pragma unroll
        for (int i = 0; i < 4; i++) {
            const int id = tid + i * 128;
            const int row = id >> 3;
            const int ch = id & 7;
            const uint32_t off = row * 128 + ch * 16;
            const uint32_t sw = off ^ ((off >> 3) & 0x70);
            const size_t g = base + (size_t)(jb * 64 + row) * HD + ch * 8;
            sts128(sKh + sw, *(const uint4*)(g_Kh + g));
            sts128(sKl + sw, *(const uint4*)(g_Kl + g));
            sts128(sVh + sw, *(const uint4*)(g_Vh + g));
            sts128(sVl + sw, *(const uint4*)(g_Vl + g));
        }
        __syncthreads();

        // S = Q @ K^T (split 3-MMA), 16x64 per warp
        float sv[8][4];
#pragma unroll
        for (int nf = 0; nf < 8; nf++)
#pragma unroll
            for (int q = 0; q < 4; q++) sv[nf][q] = 0.0f;

#pragma unroll
        for (int np = 0; np < 4; np++) {
#pragma unroll
            for (int ks = 0; ks < 4; ks++) {
                const uint32_t off = (uint32_t)(np * 16 + frow) * 128 + (ks * 16 + koff) * 2;
                const uint32_t sw = off ^ ((off >> 3) & 0x70);
                uint32_t khf[4], klf[4];
                ldsm4(khf, sKh + sw);
                ldsm4(klf, sKl + sw);
                mma16816(sv[np * 2 + 0], qh[ks], khf[0], khf[2]);
                mma16816(sv[np * 2 + 0], qh[ks], klf[0], klf[2]);
                mma16816(sv[np * 2 + 0], ql[ks], khf[0], khf[2]);
                mma16816(sv[np * 2 + 1], qh[ks], khf[1], khf[3]);
                mma16816(sv[np * 2 + 1], qh[ks], klf[1], klf[3]);
                mma16816(sv[np * 2 + 1], ql[ks], khf[1], khf[3]);
            }
        }

        // scale + causal mask (diagonal tile only)
#pragma unroll
        for (int nf = 0; nf < 8; nf++)
#pragma unroll
            for (int q = 0; q < 4; q++) sv[nf][q] *= 0.125f;

        if (jb == qb) {
#pragma unroll
            for (int nf = 0; nf < 8; nf++) {
                const int k0 = nf * 8 + cj;
                const int q0 = wm + r;
                if (k0     > q0)     sv[nf][0] = -1e30f;
                if (k0 + 1 > q0)     sv[nf][1] = -1e30f;
                if (k0     > q0 + 8) sv[nf][2] = -1e30f;
                if (k0 + 1 > q0 + 8) sv[nf][3] = -1e30f;
            }
        }

        // online softmax, rows r (regs 0,1) and r+8 (regs 2,3)
        float mt0 = -1e30f, mt1 = -1e30f;
#pragma unroll
        for (int nf = 0; nf < 8; nf++) {
            mt0 = fmaxf(mt0, fmaxf(sv[nf][0], sv[nf][1]));
            mt1 = fmaxf(mt1, fmaxf(sv[nf][2], sv[nf][3]));
        }
        mt0 = fmaxf(mt0, __shfl_xor_sync(0xffffffffu, mt0, 1));
        mt0 = fmaxf(mt0, __shfl_xor_sync(0xffffffffu, mt0, 2));
        mt1 = fmaxf(mt1, __shfl_xor_sync(0xffffffffu, mt1, 1));
        mt1 = fmaxf(mt1, __shfl_xor_sync(0xffffffffu, mt1, 2));
        const float mn0 = fmaxf(m0, mt0);
        const float mn1 = fmaxf(m1, mt1);

        float ls0 = 0.0f, ls1 = 0.0f;
#pragma unroll
        for (int nf = 0; nf < 8; nf++) {
            sv[nf][0] = __expf(sv[nf][0] - mn0);
            sv[nf][1] = __expf(sv[nf][1] - mn0);
            sv[nf][2] = __expf(sv[nf][2] - mn1);
            sv[nf][3] = __expf(sv[nf][3] - mn1);
            ls0 += sv[nf][0] + sv[nf][1];
            ls1 += sv[nf][2] + sv[nf][3];
        }
        ls0 += __shfl_xor_sync(0xffffffffu, ls0, 1);
        ls0 += __shfl_xor_sync(0xffffffffu, ls0, 2);
        ls1 += __shfl_xor_sync(0xffffffffu, ls1, 1);
        ls1 += __shfl_xor_sync(0xffffffffu, ls1, 2);

        const float a0 = __expf(m0 - mn0);
        const float a1 = __expf(m1 - mn1);
        l0 = l0 * a0 + ls0;
        l1 = l1 * a1 + ls1;
        m0 = mn0; m1 = mn1;
#pragma unroll
        for (int nf = 0; nf < 8; nf++) {
            o[nf][0] *= a0; o[nf][1] *= a0;
            o[nf][2] *= a1; o[nf][3] *= a1;
        }

        // O += P @ V (split 3-MMA), P fragments straight from accumulators
#pragma unroll
        for (int kp = 0; kp < 4; kp++) {
            uint32_t Ph[4], Pl[4];
            split_pack(sv[2 * kp][0],     sv[2 * kp][1],     Ph[0], Pl[0]);
            split_pack(sv[2 * kp][2],     sv[2 * kp][3],     Ph[1], Pl[1]);
            split_pack(sv[2 * kp + 1][0], sv[2 * kp + 1][1], Ph[2], Pl[2]);
            split_pack(sv[2 * kp + 1][2], sv[2 * kp + 1][3], Ph[3], Pl[3]);
#pragma unroll
            for (int hp = 0; hp < 4; hp++) {
                const uint32_t off = (uint32_t)(kp * 16 + frow) * 128 + (hp * 16 + koff) * 2;
                const uint32_t sw = off ^ ((off >> 3) & 0x70);
                uint32_t vhf[4], vlf[4];
                ldsm4t(vhf, sVh + sw);
                ldsm4t(vlf, sVl + sw);
                mma16816(o[hp * 2 + 0], Ph, vhf[0], vhf[1]);
                mma16816(o[hp * 2 + 0], Ph, vlf[0], vlf[1]);
                mma16816(o[hp * 2 + 0], Pl, vhf[0], vhf[1]);
                mma16816(o[hp * 2 + 1], Ph, vhf[2], vhf[3]);
                mma16816(o[hp * 2 + 1], Ph, vlf[2], vlf[3]);
                mma16816(o[hp * 2 + 1], Pl, vhf[2], vhf[3]);
            }
        }
        __syncthreads();
    }

    // epilogue: normalize, scatter to concat [b][s][d]
    const float inv0 = 1.0f / l0;
    const float inv1 = 1.0f / l1;
    const int q0 = qb * 64 + wm + r;
    const int q1 = q0 + 8;
#pragma unroll
    for (int nf = 0; nf < 8; nf++) {
        const int col = h * HD + nf * 8 + cj;
        float2 v0; v0.x = o[nf][0] * inv0; v0.y = o[nf][1] * inv0;
        float2 v1; v1.x = o[nf][2] * inv1; v1.y = o[nf][3] * inv1;
        *(float2*)(g_Ctx + ((size_t)b * SEQ + q0) * DM + col) = v0;
        *(float2*)(g_Ctx + ((size_t)b * SEQ + q1) * DM + col) = v1;
    }
}

// ---------------- launch ----------------
extern "C" void kernel_launch(void* const* d_in, const int* in_sizes, int n_in,
                              void* d_out, int out_size)
{
    const float* x  = (const float*)d_in[0];
    const float* Wq = (const float*)d_in[1];
    const float* Wk = (const float*)d_in[2];
    const float* Wv = (const float*)d_in[3];
    const float* Wo = (const float*)d_in[4];
    float* out = (float*)d_out;

    float* pCtx;
    cudaGetSymbolAddress((void**)&pCtx, g_Ctx);
    __nv_bfloat16 *pAh, *pAl, *pWh, *pWl, *pQh, *pQl, *pKh, *pKl, *pVh, *pVl;
    cudaGetSymbolAddress((void**)&pAh, g_Ah);
    cudaGetSymbolAddress((void**)&pAl, g_Al);
    cudaGetSymbolAddress((void**)&pWh, g_Wh);
    cudaGetSymbolAddress((void**)&pWl, g_Wl);
    cudaGetSymbolAddress((void**)&pQh, g_Qh);
    cudaGetSymbolAddress((void**)&pQl, g_Ql);
    cudaGetSymbolAddress((void**)&pKh, g_Kh);
    cudaGetSymbolAddress((void**)&pKl, g_Kl);
    cudaGetSymbolAddress((void**)&pVh, g_Vh);
    cudaGetSymbolAddress((void**)&pVl, g_Vl);

    const int GSMEM = 65536 + 256;
    cudaFuncSetAttribute(tgemm_kernel<0>, cudaFuncAttributeMaxDynamicSharedMemorySize, GSMEM);
    cudaFuncSetAttribute(tgemm_kernel<1>, cudaFuncAttributeMaxDynamicSharedMemorySize, GSMEM);
    cudaFuncSetAttribute(tgemm_kernel<2>, cudaFuncAttributeMaxDynamicSharedMemorySize, GSMEM);

    rope_table_kernel<<<(SEQ * 32 + 255) / 256, 256>>>();

    const int nx4 = BATCH * SEQ * DM / 4;
    const int nw4 = DM * DM / 4;
    split_kernel<<<(nx4 + 255) / 256, 256>>>(x,  pAh, pAl, nx4);
    split_kernel<<<(nw4 + 255) / 256, 256>>>(Wq, pWh + 0 * (size_t)DM * DM, pWl + 0 * (size_t)DM * DM, nw4);
    split_kernel<<<(nw4 + 255) / 256, 256>>>(Wk, pWh + 1 * (size_t)DM * DM, pWl + 1 * (size_t)DM * DM, nw4);
    split_kernel<<<(nw4 + 255) / 256, 256>>>(Wv, pWh + 2 * (size_t)DM * DM, pWl + 2 * (size_t)DM * DM, nw4);
    split_kernel<<<(nw4 + 255) / 256, 256>>>(Wo, pWh + 3 * (size_t)DM * DM, pWl + 3 * (size_t)DM * DM, nw4);

    dim3 ggrid(DM / 128, BATCH * SEQ / 128);  // (8, 32)
    tgemm_kernel<1><<<ggrid, 256, GSMEM>>>(pAh, pAl, pWh + 0 * (size_t)DM * DM, pWl + 0 * (size_t)DM * DM,
                                           nullptr, pQh, pQl);
    tgemm_kernel<1><<<ggrid, 256, GSMEM>>>(pAh, pAl, pWh + 1 * (size_t)DM * DM, pWl + 1 * (size_t)DM * DM,
                                           nullptr, pKh, pKl);
    tgemm_kernel<2><<<ggrid, 256, GSMEM>>>(pAh, pAl, pWh + 2 * (size_t)DM * DM, pWl + 2 * (size_t)DM * DM,
                                           nullptr, pVh, pVl);

    const int ASMEM = 49152 + 256;
    cudaFuncSetAttribute(attn_hmma_kernel, cudaFuncAttributeMaxDynamicSharedMemorySize, ASMEM);
    attn_hmma_kernel<<<dim3(SEQ / 64, BATCH * NH), 128, ASMEM>>>();

    split_kernel<<<(nx4 + 255) / 256, 256>>>(pCtx, pAh, pAl, nx4);
    tgemm_kernel<0><<<ggrid, 256, GSMEM>>>(pAh, pAl, pWh + 3 * (size_t)DM * DM, pWl + 3 * (size_t)DM * DM,
                                           out, nullptr, nullptr);
}

// round 8
// speedup vs baseline: 3.3866x; 1.2280x over previous
#include <cuda_runtime.h>
#include <cuda_bf16.h>
#include <math.h>
#include <stdint.h>

#define BATCH 2
#define SEQ 2048
#define DM 1024
#define NH 16
#define HD 64

// ---------------- scratch (static device globals; no allocs allowed) ----------------
__device__ float g_cos[SEQ * (HD / 2)];
__device__ float g_sin[SEQ * (HD / 2)];

// split-bf16 Q/K/V, [b][h][s][hd]
__device__ __nv_bfloat16 g_Qh[(size_t)BATCH * NH * SEQ * HD];
__device__ __nv_bfloat16 g_Ql[(size_t)BATCH * NH * SEQ * HD];
__device__ __nv_bfloat16 g_Kh[(size_t)BATCH * NH * SEQ * HD];
__device__ __nv_bfloat16 g_Kl[(size_t)BATCH * NH * SEQ * HD];
__device__ __nv_bfloat16 g_Vh[(size_t)BATCH * NH * SEQ * HD];
__device__ __nv_bfloat16 g_Vl[(size_t)BATCH * NH * SEQ * HD];

// split-bf16 GEMM operand buffers (x for QKV projs; attention writes Ctx here)
__device__ __nv_bfloat16 g_Ah[(size_t)BATCH * SEQ * DM];
__device__ __nv_bfloat16 g_Al[(size_t)BATCH * SEQ * DM];
__device__ __nv_bfloat16 g_Wh[4][(size_t)DM * DM];       // weights hi: q,k,v,o
__device__ __nv_bfloat16 g_Wl[4][(size_t)DM * DM];       // weights lo

// ---------------- PTX helpers (generic-PTX-safe; sm_80-era features only) ---------
__device__ __forceinline__ uint32_t smem_u32(const void* p) {
    uint32_t a;
    asm("{ .reg .u64 t; cvta.to.shared.u64 t, %1; cvt.u32.u64 %0, t; }" : "=r"(a) : "l"(p));
    return a;
}

__device__ __forceinline__ void sts128(uint32_t addr, uint4 v) {
    asm volatile("st.shared.v4.b32 [%0], {%1,%2,%3,%4};"
                 :: "r"(addr), "r"(v.x), "r"(v.y), "r"(v.z), "r"(v.w) : "memory");
}

__device__ __forceinline__ void cpasync16(uint32_t dst, const void* src) {
    asm volatile("cp.async.cg.shared.global [%0], [%1], 16;" :: "r"(dst), "l"(src) : "memory");
}
__device__ __forceinline__ void cp_commit() {
    asm volatile("cp.async.commit_group;" ::: "memory");
}
template <int N>
__device__ __forceinline__ void cp_wait() {
    asm volatile("cp.async.wait_group %0;" :: "n"(N) : "memory");
}

__device__ __forceinline__ void ldsm4(uint32_t* r, uint32_t addr) {
    asm volatile("ldmatrix.sync.aligned.m8n8.x4.shared.b16 {%0,%1,%2,%3}, [%4];"
                 : "=r"(r[0]), "=r"(r[1]), "=r"(r[2]), "=r"(r[3]) : "r"(addr));
}

__device__ __forceinline__ void ldsm4t(uint32_t* r, uint32_t addr) {
    asm volatile("ldmatrix.sync.aligned.m8n8.x4.trans.shared.b16 {%0,%1,%2,%3}, [%4];"
                 : "=r"(r[0]), "=r"(r[1]), "=r"(r[2]), "=r"(r[3]) : "r"(addr));
}

__device__ __forceinline__ void mma16816(float* c, const uint32_t* a, uint32_t b0, uint32_t b1) {
    asm volatile(
        "mma.sync.aligned.m16n8k16.row.col.f32.bf16.bf16.f32 "
        "{%0,%1,%2,%3}, {%4,%5,%6,%7}, {%8,%9}, {%0,%1,%2,%3};"
        : "+f"(c[0]), "+f"(c[1]), "+f"(c[2]), "+f"(c[3])
        : "r"(a[0]), "r"(a[1]), "r"(a[2]), "r"(a[3]), "r"(b0), "r"(b1));
}

// split two fp32 -> packed bf16x2 hi + bf16x2 lo (element0 in low half)
__device__ __forceinline__ void split_pack(float a, float b, uint32_t& hi, uint32_t& lo) {
    __nv_bfloat16 ha = __float2bfloat16(a), hb = __float2bfloat16(b);
    __nv_bfloat16 la = __float2bfloat16(a - __bfloat162float(ha));
    __nv_bfloat16 lb = __float2bfloat16(b - __bfloat162float(hb));
    __nv_bfloat162 H; H.x = ha; H.y = hb;
    __nv_bfloat162 L; L.x = la; L.y = lb;
    hi = *(uint32_t*)&H;
    lo = *(uint32_t*)&L;
}

// ---------------- RoPE table ----------------
__global__ void rope_table_kernel() {
    int idx = blockIdx.x * blockDim.x + threadIdx.x;
    if (idx >= SEQ * (HD / 2)) return;
    int s = idx >> 5;          // HD/2 = 32
    int p = idx & 31;
    float freq = powf(10000.0f, -(float)(2 * p) / (float)HD);
    float ang = (float)s * freq;
    g_cos[idx] = cosf(ang);
    g_sin[idx] = sinf(ang);
}

// ---------------- fp32 -> bf16 hi/lo split ----------------
__global__ void split_kernel(const float* __restrict__ x,
                             __nv_bfloat16* __restrict__ hi,
                             __nv_bfloat16* __restrict__ lo, int n4) {
    int i = blockIdx.x * blockDim.x + threadIdx.x;
    if (i >= n4) return;
    float4 v = ((const float4*)x)[i];
    __nv_bfloat16 h0 = __float2bfloat16(v.x);
    __nv_bfloat16 h1 = __float2bfloat16(v.y);
    __nv_bfloat16 h2 = __float2bfloat16(v.z);
    __nv_bfloat16 h3 = __float2bfloat16(v.w);
    __nv_bfloat16 l0 = __float2bfloat16(v.x - __bfloat162float(h0));
    __nv_bfloat16 l1 = __float2bfloat16(v.y - __bfloat162float(h1));
    __nv_bfloat16 l2 = __float2bfloat16(v.z - __bfloat162float(h2));
    __nv_bfloat16 l3 = __float2bfloat16(v.w - __bfloat162float(h3));
    __nv_bfloat162 H0; H0.x = h0; H0.y = h1;
    __nv_bfloat162 H1; H1.x = h2; H1.y = h3;
    __nv_bfloat162 L0; L0.x = l0; L0.y = l1;
    __nv_bfloat162 L1; L1.x = l2; L1.y = l3;
    ((__nv_bfloat162*)hi)[2 * i]     = H0;
    ((__nv_bfloat162*)hi)[2 * i + 1] = H1;
    ((__nv_bfloat162*)lo)[2 * i]     = L0;
    ((__nv_bfloat162*)lo)[2 * i + 1] = L1;
}

// ---------------- HMMA split-bf16 GEMM, cp.async double-buffered ----------------
// C = A(MxK) @ B(NxK)^T. Block tile 128x128, 8 warps, warp tile 32x64, K-chunk 64.
// MODE 0: row-major fp32 C[M][N]
// MODE 1: RoPE, then split-bf16 scatter into Ch/Cl [b][h][s][hd]
// MODE 2: split-bf16 scatter into Ch/Cl (no RoPE)
template <int MODE>
__global__ void __launch_bounds__(256) tgemm_kernel(const __nv_bfloat16* __restrict__ Ah,
                                                    const __nv_bfloat16* __restrict__ Al,
                                                    const __nv_bfloat16* __restrict__ Bh,
                                                    const __nv_bfloat16* __restrict__ Bl,
                                                    float* __restrict__ C,
                                                    __nv_bfloat16* __restrict__ Ch,
                                                    __nv_bfloat16* __restrict__ Cl)
{
    constexpr int Kdim = DM;
    constexpr int NCH = Kdim / 64;         // 16 K-chunks
    extern __shared__ char smem[];
    const int tid = threadIdx.x;
    const int wid = tid >> 5;
    const int l   = tid & 31;
    const int bm = blockIdx.y * 128;
    const int bn = blockIdx.x * 128;

    const uint32_t tb = (smem_u32(smem) + 127) & ~127u;
    // stage s at tb + s*65536; tiles Ah,Al,Bh,Bl at +0,+16384,+32768,+49152

    const int wm = (wid >> 1) * 32;
    const int wn = (wid & 1) * 64;

    float acc[2][8][4];
#pragma unroll
    for (int mf = 0; mf < 2; mf++)
#pragma unroll
        for (int nf = 0; nf < 8; nf++)
#pragma unroll
            for (int q = 0; q < 4; q++) acc[mf][nf][q] = 0.0f;

    const int frow = (l & 7) + ((l >> 3) & 1) * 8;
    const int koff = ((l >> 4) & 1) * 8;

    // async-load one K-chunk into a stage
    auto load_chunk = [&](int c, int st) {
        const int k0 = c * 64;
        const uint32_t s0 = tb + st * 65536;
#pragma unroll
        for (int i = 0; i < 4; i++) {
            const int id = tid + i * 256;
            const int row = id >> 3;
            const int ch = id & 7;
            const uint32_t off = row * 128 + ch * 16;
            const uint32_t sw = off ^ ((off >> 3) & 0x70);
            const size_t ga = (size_t)(bm + row) * Kdim + k0 + ch * 8;
            const size_t gb = (size_t)(bn + row) * Kdim + k0 + ch * 8;
            cpasync16(s0 + sw,         Ah + ga);
            cpasync16(s0 + 16384 + sw, Al + ga);
            cpasync16(s0 + 32768 + sw, Bh + gb);
            cpasync16(s0 + 49152 + sw, Bl + gb);
        }
        cp_commit();
    };

    load_chunk(0, 0);

    for (int c = 0; c < NCH; c++) {
        if (c + 1 < NCH) {
            load_chunk(c + 1, (c + 1) & 1);
            cp_wait<1>();
        } else {
            cp_wait<0>();
        }
        __syncthreads();

        const uint32_t s0 = tb + (c & 1) * 65536;
        const uint32_t sAh = s0, sAl = s0 + 16384, sBh = s0 + 32768, sBl = s0 + 49152;

#pragma unroll
        for (int ks = 0; ks < 4; ks++) {
            const int kk = ks * 16 + koff;
            uint32_t ahf[2][4], alf[2][4];
#pragma unroll
            for (int mf = 0; mf < 2; mf++) {
                const uint32_t off = (uint32_t)(wm + mf * 16 + frow) * 128 + kk * 2;
                const uint32_t sw = off ^ ((off >> 3) & 0x70);
                ldsm4(ahf[mf], sAh + sw);
                ldsm4(alf[mf], sAl + sw);
            }
#pragma unroll
            for (int np = 0; np < 4; np++) {
                const uint32_t off = (uint32_t)(wn + np * 16 + frow) * 128 + kk * 2;
                const uint32_t sw = off ^ ((off >> 3) & 0x70);
                uint32_t bhf[4], blf[4];
                ldsm4(bhf, sBh + sw);
                ldsm4(blf, sBl + sw);
#pragma unroll
                for (int mf = 0; mf < 2; mf++) {
                    mma16816(acc[mf][np * 2 + 0], ahf[mf], bhf[0], bhf[2]);
                    mma16816(acc[mf][np * 2 + 0], ahf[mf], blf[0], blf[2]);
                    mma16816(acc[mf][np * 2 + 0], alf[mf], bhf[0], bhf[2]);
                    mma16816(acc[mf][np * 2 + 1], ahf[mf], bhf[1], bhf[3]);
                    mma16816(acc[mf][np * 2 + 1], ahf[mf], blf[1], blf[3]);
                    mma16816(acc[mf][np * 2 + 1], alf[mf], bhf[1], bhf[3]);
                }
            }
        }
        __syncthreads();
    }

    const int r_lane = l >> 2;
    const int c_lane = (l & 3) * 2;
#pragma unroll
    for (int mf = 0; mf < 2; mf++) {
#pragma unroll
        for (int half = 0; half < 2; half++) {
            const int mrow = bm + wm + mf * 16 + r_lane + half * 8;
            const int b = mrow >> 11;            // SEQ = 2048
            const int s = mrow & (SEQ - 1);
#pragma unroll
            for (int nf = 0; nf < 8; nf++) {
                float e = acc[mf][nf][half * 2 + 0];
                float o = acc[mf][nf][half * 2 + 1];
                const int col = bn + wn + nf * 8 + c_lane;   // even
                if (MODE == 0) {
                    float2 v; v.x = e; v.y = o;
                    *(float2*)(C + (size_t)mrow * DM + col) = v;
                } else {
                    const int h = col >> 6;
                    const int d0 = col & 63;
                    if (MODE == 1) {
                        const int p = d0 >> 1;
                        const float cs = g_cos[s * 32 + p];
                        const float sn = g_sin[s * 32 + p];
                        const float re = e * cs - o * sn;
                        const float ro = e * sn + o * cs;
                        e = re; o = ro;
                    }
                    const size_t idx = (((size_t)b * NH + h) * SEQ + s) * HD + d0;
                    uint32_t hi, lo;
                    split_pack(e, o, hi, lo);
                    *(uint32_t*)(Ch + idx) = hi;
                    *(uint32_t*)(Cl + idx) = lo;
                }
            }
        }
    }
}

// ---------------- HMMA flash attention (split-bf16, causal, cp.async pipelined) ----
// grid (SEQ/64, BATCH*NH), 128 threads = 4 warps x 16 query rows.
// Output: split-bf16 directly into Oh/Ol (concat [b][s][d] layout).
__global__ void __launch_bounds__(128) attn_hmma_kernel(__nv_bfloat16* __restrict__ Oh,
                                                        __nv_bfloat16* __restrict__ Ol)
{
    const int qb = blockIdx.x;
    const int bh = blockIdx.y;
    const int b  = bh >> 4;
    const int h  = bh & 15;
    const size_t base = (size_t)bh * SEQ * HD;

    extern __shared__ char smem[];
    const uint32_t tb  = (smem_u32(smem) + 127) & ~127u;
    const uint32_t sQh = tb;
    const uint32_t sQl = tb + 8192;
    const uint32_t kvb = tb + 16384;   // stage s: kvb + s*32768; Kh,Kl,Vh,Vl at +0,8192,16384,24576

    const int tid = threadIdx.x;
    const int wid = tid >> 5;
    const int l   = tid & 31;
    const int wm  = wid * 16;
    const int frow = (l & 7) + ((l >> 3) & 1) * 8;
    const int koff = ((l >> 4) & 1) * 8;
    const int r  = l >> 2;
    const int cj = (l & 3) * 2;

    auto load_kv = [&](int jb, int st) {
        const uint32_t s0 = kvb + st * 32768;
#pragma unroll
        for (int i = 0; i < 4; i++) {
            const int id = tid + i * 128;
            const int row = id >> 3;
            const int ch = id & 7;
            const uint32_t off = row * 128 + ch * 16;
            const uint32_t sw = off ^ ((off >> 3) & 0x70);
            const size_t g = base + (size_t)(jb * 64 + row) * HD + ch * 8;
            cpasync16(s0 + sw,         g_Kh + g);
            cpasync16(s0 + 8192 + sw,  g_Kl + g);
            cpasync16(s0 + 16384 + sw, g_Vh + g);
            cpasync16(s0 + 24576 + sw, g_Vl + g);
        }
        cp_commit();
    };

    load_kv(0, 0);

    // load Q tile (64 x 64 bf16, hi+lo) swizzled
#pragma unroll
    for (int i = 0; i < 4; i++) {
        const int id = tid + i * 128;
        const int row = id >> 3;
        const int ch = id & 7;
        const uint32_t off = row * 128 + ch * 16;
        const uint32_t sw = off ^ ((off >> 3) & 0x70);
        const size_t g = base + (size_t)(qb * 64 + row) * HD + ch * 8;
        sts128(sQh + sw, *(const uint4*)(g_Qh + g));
        sts128(sQl + sw, *(const uint4*)(g_Ql + g));
    }
    __syncthreads();

    // preload Q fragments (16 rows x 64 k)
    uint32_t qh[4][4], ql[4][4];
#pragma unroll
    for (int ks = 0; ks < 4; ks++) {
        const uint32_t off = (uint32_t)(wm + frow) * 128 + (ks * 16 + koff) * 2;
        const uint32_t sw = off ^ ((off >> 3) & 0x70);
        ldsm4(qh[ks], sQh + sw);
        ldsm4(ql[ks], sQl + sw);
    }

    float m0 = -1e30f, m1 = -1e30f, l0 = 0.0f, l1 = 0.0f;
    float o[8][4];
#pragma unroll
    for (int nf = 0; nf < 8; nf++)
#pragma unroll
        for (int q = 0; q < 4; q++) o[nf][q] = 0.0f;

    for (int jb = 0; jb <= qb; jb++) {
        if (jb + 1 <= qb) {
            load_kv(jb + 1, (jb + 1) & 1);
            cp_wait<1>();
        } else {
            cp_wait<0>();
        }
        __syncthreads();

        const uint32_t s0 = kvb + (jb & 1) * 32768;
        const uint32_t sKh = s0, sKl = s0 + 8192, sVh = s0 + 16384, sVl = s0 + 24576;

        // S = Q @ K^T (split 3-MMA), 16x64 per warp
        float sv[8][4];
#pragma unroll
        for (int nf = 0; nf < 8; nf++)
#pragma unroll
            for (int q = 0; q < 4; q++) sv[nf][q] = 0.0f;

#pragma unroll
        for (int np = 0; np < 4; np++) {
#pragma unroll
            for (int ks = 0; ks < 4; ks++) {
                const uint32_t off = (uint32_t)(np * 16 + frow) * 128 + (ks * 16 + koff) * 2;
                const uint32_t sw = off ^ ((off >> 3) & 0x70);
                uint32_t khf[4], klf[4];
                ldsm4(khf, sKh + sw);
                ldsm4(klf, sKl + sw);
                mma16816(sv[np * 2 + 0], qh[ks], khf[0], khf[2]);
                mma16816(sv[np * 2 + 0], qh[ks], klf[0], klf[2]);
                mma16816(sv[np * 2 + 0], ql[ks], khf[0], khf[2]);
                mma16816(sv[np * 2 + 1], qh[ks], khf[1], khf[3]);
                mma16816(sv[np * 2 + 1], qh[ks], klf[1], klf[3]);
                mma16816(sv[np * 2 + 1], ql[ks], khf[1], khf[3]);
            }
        }

        // scale + causal mask (diagonal tile only)
#pragma unroll
        for (int nf = 0; nf < 8; nf++)
#pragma unroll
            for (int q = 0; q < 4; q++) sv[nf][q] *= 0.125f;

        if (jb == qb) {
#pragma unroll
            for (int nf = 0; nf < 8; nf++) {
                const int k0 = nf * 8 + cj;
                const int q0 = wm + r;
                if (k0     > q0)     sv[nf][0] = -1e30f;
                if (k0 + 1 > q0)     sv[nf][1] = -1e30f;
                if (k0     > q0 + 8) sv[nf][2] = -1e30f;
                if (k0 + 1 > q0 + 8) sv[nf][3] = -1e30f;
            }
        }

        // online softmax, rows r (regs 0,1) and r+8 (regs 2,3)
        float mt0 = -1e30f, mt1 = -1e30f;
#pragma unroll
        for (int nf = 0; nf < 8; nf++) {
            mt0 = fmaxf(mt0, fmaxf(sv[nf][0], sv[nf][1]));
            mt1 = fmaxf(mt1, fmaxf(sv[nf][2], sv[nf][3]));
        }
        mt0 = fmaxf(mt0, __shfl_xor_sync(0xffffffffu, mt0, 1));
        mt0 = fmaxf(mt0, __shfl_xor_sync(0xffffffffu, mt0, 2));
        mt1 = fmaxf(mt1, __shfl_xor_sync(0xffffffffu, mt1, 1));
        mt1 = fmaxf(mt1, __shfl_xor_sync(0xffffffffu, mt1, 2));
        const float mn0 = fmaxf(m0, mt0);
        const float mn1 = fmaxf(m1, mt1);

        float ls0 = 0.0f, ls1 = 0.0f;
#pragma unroll
        for (int nf = 0; nf < 8; nf++) {
            sv[nf][0] = __expf(sv[nf][0] - mn0);
            sv[nf][1] = __expf(sv[nf][1] - mn0);
            sv[nf][2] = __expf(sv[nf][2] - mn1);
            sv[nf][3] = __expf(sv[nf][3] - mn1);
            ls0 += sv[nf][0] + sv[nf][1];
            ls1 += sv[nf][2] + sv[nf][3];
        }
        ls0 += __shfl_xor_sync(0xffffffffu, ls0, 1);
        ls0 += __shfl_xor_sync(0xffffffffu, ls0, 2);
        ls1 += __shfl_xor_sync(0xffffffffu, ls1, 1);
        ls1 += __shfl_xor_sync(0xffffffffu, ls1, 2);

        const float a0 = __expf(m0 - mn0);
        const float a1 = __expf(m1 - mn1);
        l0 = l0 * a0 + ls0;
        l1 = l1 * a1 + ls1;
        m0 = mn0; m1 = mn1;
#pragma unroll
        for (int nf = 0; nf < 8; nf++) {
            o[nf][0] *= a0; o[nf][1] *= a0;
            o[nf][2] *= a1; o[nf][3] *= a1;
        }

        // O += P @ V (split 3-MMA), P fragments straight from accumulators
#pragma unroll
        for (int kp = 0; kp < 4; kp++) {
            uint32_t Ph[4], Pl[4];
            split_pack(sv[2 * kp][0],     sv[2 * kp][1],     Ph[0], Pl[0]);
            split_pack(sv[2 * kp][2],     sv[2 * kp][3],     Ph[1], Pl[1]);
            split_pack(sv[2 * kp + 1][0], sv[2 * kp + 1][1], Ph[2], Pl[2]);
            split_pack(sv[2 * kp + 1][2], sv[2 * kp + 1][3], Ph[3], Pl[3]);
#pragma unroll
            for (int hp = 0; hp < 4; hp++) {
                const uint32_t off = (uint32_t)(kp * 16 + frow) * 128 + (hp * 16 + koff) * 2;
                const uint32_t sw = off ^ ((off >> 3) & 0x70);
                uint32_t vhf[4], vlf[4];
                ldsm4t(vhf, sVh + sw);
                ldsm4t(vlf, sVl + sw);
                mma16816(o[hp * 2 + 0], Ph, vhf[0], vhf[1]);
                mma16816(o[hp * 2 + 0], Ph, vlf[0], vlf[1]);
                mma16816(o[hp * 2 + 0], Pl, vhf[0], vhf[1]);
                mma16816(o[hp * 2 + 1], Ph, vhf[2], vhf[3]);
                mma16816(o[hp * 2 + 1], Ph, vlf[2], vlf[3]);
                mma16816(o[hp * 2 + 1], Pl, vhf[2], vhf[3]);
            }
        }
        __syncthreads();
    }

    // epilogue: normalize, split-bf16 scatter to concat [b][s][d]
    const float inv0 = 1.0f / l0;
    const float inv1 = 1.0f / l1;
    const int q0 = qb * 64 + wm + r;
    const int q1 = q0 + 8;
#pragma unroll
    for (int nf = 0; nf < 8; nf++) {
        const int col = h * HD + nf * 8 + cj;
        uint32_t hi, lo;
        split_pack(o[nf][0] * inv0, o[nf][1] * inv0, hi, lo);
        const size_t i0 = ((size_t)b * SEQ + q0) * DM + col;
        *(uint32_t*)(Oh + i0) = hi;
        *(uint32_t*)(Ol + i0) = lo;
        split_pack(o[nf][2] * inv1, o[nf][3] * inv1, hi, lo);
        const size_t i1 = ((size_t)b * SEQ + q1) * DM + col;
        *(uint32_t*)(Oh + i1) = hi;
        *(uint32_t*)(Ol + i1) = lo;
    }
}

// ---------------- launch ----------------
extern "C" void kernel_launch(void* const* d_in, const int* in_sizes, int n_in,
                              void* d_out, int out_size)
{
    const float* x  = (const float*)d_in[0];
    const float* Wq = (const float*)d_in[1];
    const float* Wk = (const float*)d_in[2];
    const float* Wv = (const float*)d_in[3];
    const float* Wo = (const float*)d_in[4];
    float* out = (float*)d_out;

    __nv_bfloat16 *pAh, *pAl, *pWh, *pWl, *pQh, *pQl, *pKh, *pKl, *pVh, *pVl;
    cudaGetSymbolAddress((void**)&pAh, g_Ah);
    cudaGetSymbolAddress((void**)&pAl, g_Al);
    cudaGetSymbolAddress((void**)&pWh, g_Wh);
    cudaGetSymbolAddress((void**)&pWl, g_Wl);
    cudaGetSymbolAddress((void**)&pQh, g_Qh);
    cudaGetSymbolAddress((void**)&pQl, g_Ql);
    cudaGetSymbolAddress((void**)&pKh, g_Kh);
    cudaGetSymbolAddress((void**)&pKl, g_Kl);
    cudaGetSymbolAddress((void**)&pVh, g_Vh);
    cudaGetSymbolAddress((void**)&pVl, g_Vl);

    const int GSMEM = 2 * 65536 + 256;          // double-buffered
    cudaFuncSetAttribute(tgemm_kernel<0>, cudaFuncAttributeMaxDynamicSharedMemorySize, GSMEM);
    cudaFuncSetAttribute(tgemm_kernel<1>, cudaFuncAttributeMaxDynamicSharedMemorySize, GSMEM);
    cudaFuncSetAttribute(tgemm_kernel<2>, cudaFuncAttributeMaxDynamicSharedMemorySize, GSMEM);

    rope_table_kernel<<<(SEQ * 32 + 255) / 256, 256>>>();

    const int nx4 = BATCH * SEQ * DM / 4;
    const int nw4 = DM * DM / 4;
    split_kernel<<<(nx4 + 255) / 256, 256>>>(x,  pAh, pAl, nx4);
    split_kernel<<<(nw4 + 255) / 256, 256>>>(Wq, pWh + 0 * (size_t)DM * DM, pWl + 0 * (size_t)DM * DM, nw4);
    split_kernel<<<(nw4 + 255) / 256, 256>>>(Wk, pWh + 1 * (size_t)DM * DM, pWl + 1 * (size_t)DM * DM, nw4);
    split_kernel<<<(nw4 + 255) / 256, 256>>>(Wv, pWh + 2 * (size_t)DM * DM, pWl + 2 * (size_t)DM * DM, nw4);
    split_kernel<<<(nw4 + 255) / 256, 256>>>(Wo, pWh + 3 * (size_t)DM * DM, pWl + 3 * (size_t)DM * DM, nw4);

    dim3 ggrid(DM / 128, BATCH * SEQ / 128);  // (8, 32)
    tgemm_kernel<1><<<ggrid, 256, GSMEM>>>(pAh, pAl, pWh + 0 * (size_t)DM * DM, pWl + 0 * (size_t)DM * DM,
                                           nullptr, pQh, pQl);
    tgemm_kernel<1><<<ggrid, 256, GSMEM>>>(pAh, pAl, pWh + 1 * (size_t)DM * DM, pWl + 1 * (size_t)DM * DM,
                                           nullptr, pKh, pKl);
    tgemm_kernel<2><<<ggrid, 256, GSMEM>>>(pAh, pAl, pWh + 2 * (size_t)DM * DM, pWl + 2 * (size_t)DM * DM,
                                           nullptr, pVh, pVl);

    const int ASMEM = 16384 + 2 * 32768 + 256;  // Q + double-buffered KV
    cudaFuncSetAttribute(attn_hmma_kernel, cudaFuncAttributeMaxDynamicSharedMemorySize, ASMEM);
    attn_hmma_kernel<<<dim3(SEQ / 64, BATCH * NH), 128, ASMEM>>>(pAh, pAl);

    tgemm_kernel<0><<<ggrid, 256, GSMEM>>>(pAh, pAl, pWh + 3 * (size_t)DM * DM, pWl + 3 * (size_t)DM * DM,
                                           out, nullptr, nullptr);
}

// round 9
// speedup vs baseline: 3.4787x; 1.0272x over previous
#include <cuda_runtime.h>
#include <cuda_bf16.h>
#include <math.h>
#include <stdint.h>

#define BATCH 2
#define SEQ 2048
#define DM 1024
#define NH 16
#define HD 64

// ---------------- scratch (static device globals; no allocs allowed) ----------------
__device__ float g_cos[SEQ * (HD / 2)];
__device__ float g_sin[SEQ * (HD / 2)];

// split-bf16 Q/K/V, [b][h][s][hd]
__device__ __nv_bfloat16 g_Qh[(size_t)BATCH * NH * SEQ * HD];
__device__ __nv_bfloat16 g_Ql[(size_t)BATCH * NH * SEQ * HD];
__device__ __nv_bfloat16 g_Kh[(size_t)BATCH * NH * SEQ * HD];
__device__ __nv_bfloat16 g_Kl[(size_t)BATCH * NH * SEQ * HD];
__device__ __nv_bfloat16 g_Vh[(size_t)BATCH * NH * SEQ * HD];
__device__ __nv_bfloat16 g_Vl[(size_t)BATCH * NH * SEQ * HD];

// split-bf16 GEMM operand buffers (x for QKV projs; attention writes Ctx here)
__device__ __nv_bfloat16 g_Ah[(size_t)BATCH * SEQ * DM];
__device__ __nv_bfloat16 g_Al[(size_t)BATCH * SEQ * DM];
__device__ __nv_bfloat16 g_Wh[4][(size_t)DM * DM];       // weights hi: q,k,v,o
__device__ __nv_bfloat16 g_Wl[4][(size_t)DM * DM];       // weights lo

// ---------------- PTX helpers (generic-PTX-safe; sm_80-era features only) ---------
__device__ __forceinline__ uint32_t smem_u32(const void* p) {
    uint32_t a;
    asm("{ .reg .u64 t; cvta.to.shared.u64 t, %1; cvt.u32.u64 %0, t; }" : "=r"(a) : "l"(p));
    return a;
}

__device__ __forceinline__ void sts128(uint32_t addr, uint4 v) {
    asm volatile("st.shared.v4.b32 [%0], {%1,%2,%3,%4};"
                 :: "r"(addr), "r"(v.x), "r"(v.y), "r"(v.z), "r"(v.w) : "memory");
}

__device__ __forceinline__ void cpasync16(uint32_t dst, const void* src) {
    asm volatile("cp.async.cg.shared.global [%0], [%1], 16;" :: "r"(dst), "l"(src) : "memory");
}
__device__ __forceinline__ void cp_commit() {
    asm volatile("cp.async.commit_group;" ::: "memory");
}
template <int N>
__device__ __forceinline__ void cp_wait() {
    asm volatile("cp.async.wait_group %0;" :: "n"(N) : "memory");
}

__device__ __forceinline__ void ldsm4(uint32_t* r, uint32_t addr) {
    asm volatile("ldmatrix.sync.aligned.m8n8.x4.shared.b16 {%0,%1,%2,%3}, [%4];"
                 : "=r"(r[0]), "=r"(r[1]), "=r"(r[2]), "=r"(r[3]) : "r"(addr));
}

__device__ __forceinline__ void ldsm4t(uint32_t* r, uint32_t addr) {
    asm volatile("ldmatrix.sync.aligned.m8n8.x4.trans.shared.b16 {%0,%1,%2,%3}, [%4];"
                 : "=r"(r[0]), "=r"(r[1]), "=r"(r[2]), "=r"(r[3]) : "r"(addr));
}

__device__ __forceinline__ void mma16816(float* c, const uint32_t* a, uint32_t b0, uint32_t b1) {
    asm volatile(
        "mma.sync.aligned.m16n8k16.row.col.f32.bf16.bf16.f32 "
        "{%0,%1,%2,%3}, {%4,%5,%6,%7}, {%8,%9}, {%0,%1,%2,%3};"
        : "+f"(c[0]), "+f"(c[1]), "+f"(c[2]), "+f"(c[3])
        : "r"(a[0]), "r"(a[1]), "r"(a[2]), "r"(a[3]), "r"(b0), "r"(b1));
}

// split two fp32 -> packed bf16x2 hi + bf16x2 lo (element0 in low half)
__device__ __forceinline__ void split_pack(float a, float b, uint32_t& hi, uint32_t& lo) {
    __nv_bfloat16 ha = __float2bfloat16(a), hb = __float2bfloat16(b);
    __nv_bfloat16 la = __float2bfloat16(a - __bfloat162float(ha));
    __nv_bfloat16 lb = __float2bfloat16(b - __bfloat162float(hb));
    __nv_bfloat162 H; H.x = ha; H.y = hb;
    __nv_bfloat162 L; L.x = la; L.y = lb;
    hi = *(uint32_t*)&H;
    lo = *(uint32_t*)&L;
}

// swizzle for 64-byte rows (GEMM tiles): XOR row bits[1:2] into chunk bits[4:5].
// Maps the 8 rows of each ldmatrix phase to 8 distinct 16B slots per 128B line.
__device__ __forceinline__ uint32_t sw64(uint32_t off) {
    return off ^ (((off >> 7) & 3u) << 4);
}
// swizzle for 128-byte rows (attention tiles)
__device__ __forceinline__ uint32_t sw128(uint32_t off) {
    return off ^ ((off >> 3) & 0x70u);
}

// ---------------- RoPE table ----------------
__global__ void rope_table_kernel() {
    int idx = blockIdx.x * blockDim.x + threadIdx.x;
    if (idx >= SEQ * (HD / 2)) return;
    int s = idx >> 5;          // HD/2 = 32
    int p = idx & 31;
    float freq = powf(10000.0f, -(float)(2 * p) / (float)HD);
    float ang = (float)s * freq;
    g_cos[idx] = cosf(ang);
    g_sin[idx] = sinf(ang);
}

// ---------------- fp32 -> bf16 hi/lo split (single tensor) ----------------
__global__ void split_kernel(const float* __restrict__ x,
                             __nv_bfloat16* __restrict__ hi,
                             __nv_bfloat16* __restrict__ lo, int n4) {
    int i = blockIdx.x * blockDim.x + threadIdx.x;
    if (i >= n4) return;
    float4 v = ((const float4*)x)[i];
    uint32_t h0, l0, h1, l1;
    split_pack(v.x, v.y, h0, l0);
    split_pack(v.z, v.w, h1, l1);
    ((uint32_t*)hi)[2 * i]     = h0;
    ((uint32_t*)hi)[2 * i + 1] = h1;
    ((uint32_t*)lo)[2 * i]     = l0;
    ((uint32_t*)lo)[2 * i + 1] = l1;
}

// all four weight matrices in one launch
__global__ void split4_kernel(const float* __restrict__ W0, const float* __restrict__ W1,
                              const float* __restrict__ W2, const float* __restrict__ W3,
                              __nv_bfloat16* __restrict__ hi, __nv_bfloat16* __restrict__ lo,
                              int n4) {
    int i = blockIdx.x * blockDim.x + threadIdx.x;
    if (i >= 4 * n4) return;
    const int w = i / n4;
    const int j = i - w * n4;
    const float* W = (w == 0) ? W0 : (w == 1) ? W1 : (w == 2) ? W2 : W3;
    float4 v = ((const float4*)W)[j];
    uint32_t h0, l0, h1, l1;
    split_pack(v.x, v.y, h0, l0);
    split_pack(v.z, v.w, h1, l1);
    const size_t base = (size_t)w * (DM * DM / 2);   // in uint32 units
    ((uint32_t*)hi)[base + 2 * j]     = h0;
    ((uint32_t*)hi)[base + 2 * j + 1] = h1;
    ((uint32_t*)lo)[base + 2 * j]     = l0;
    ((uint32_t*)lo)[base + 2 * j + 1] = l1;
}

// ---------------- HMMA split-bf16 GEMM, 3-stage cp.async, K-chunk 32 ----------------
// C = A(MxK) @ B(NxK)^T. Block tile 128x128, 8 warps, warp tile 32x64.
// MODE 0: row-major fp32 C[M][N]  (O projection)
// MODE 3: fused QKV — blockIdx.z selects weight/output; z<2 applies RoPE.
template <int MODE>
__global__ void __launch_bounds__(256, 2) tgemm_kernel(const __nv_bfloat16* __restrict__ Ah,
                                                       const __nv_bfloat16* __restrict__ Al,
                                                       const __nv_bfloat16* __restrict__ Bh0,
                                                       const __nv_bfloat16* __restrict__ Bl0,
                                                       float* __restrict__ C,
                                                       __nv_bfloat16* __restrict__ Qh,
                                                       __nv_bfloat16* __restrict__ Ql,
                                                       __nv_bfloat16* __restrict__ Kh,
                                                       __nv_bfloat16* __restrict__ Kl,
                                                       __nv_bfloat16* __restrict__ Vh,
                                                       __nv_bfloat16* __restrict__ Vl)
{
    constexpr int Kdim = DM;
    constexpr int NCH = Kdim / 32;         // 32 K-chunks of 32
    extern __shared__ char smem[];
    const int tid = threadIdx.x;
    const int wid = tid >> 5;
    const int l   = tid & 31;
    const int bm = blockIdx.y * 128;
    const int bn = blockIdx.x * 128;

    const __nv_bfloat16* Bh = Bh0;
    const __nv_bfloat16* Bl = Bl0;
    if (MODE == 3) {
        const size_t woff = (size_t)blockIdx.z * DM * DM;
        Bh = Bh0 + woff;
        Bl = Bl0 + woff;
    }

    const uint32_t tb = (smem_u32(smem) + 127) & ~127u;
    // stage s at tb + s*32768; tiles Ah,Al,Bh,Bl at +0,+8192,+16384,+24576 (128 rows x 64B)

    const int wm = (wid >> 1) * 32;
    const int wn = (wid & 1) * 64;

    float acc[2][8][4];
#pragma unroll
    for (int mf = 0; mf < 2; mf++)
#pragma unroll
        for (int nf = 0; nf < 8; nf++)
#pragma unroll
            for (int q = 0; q < 4; q++) acc[mf][nf][q] = 0.0f;

    const int frow = (l & 7) + ((l >> 3) & 1) * 8;
    const int koff = ((l >> 4) & 1) * 8;

    // async-load one K-chunk (32 wide) into a stage
    auto load_chunk = [&](int c, int st) {
        const int k0 = c * 32;
        const uint32_t s0 = tb + st * 32768;
#pragma unroll
        for (int i = 0; i < 2; i++) {
            const int id = tid + i * 256;
            const int row = id >> 2;            // 0..127
            const int ch = id & 3;              // 0..3 (16B chunks)
            const uint32_t sw = sw64((uint32_t)row * 64 + ch * 16);
            const size_t ga = (size_t)(bm + row) * Kdim + k0 + ch * 8;
            const size_t gb = (size_t)(bn + row) * Kdim + k0 + ch * 8;
            cpasync16(s0 + sw,         Ah + ga);
            cpasync16(s0 + 8192 + sw,  Al + ga);
            cpasync16(s0 + 16384 + sw, Bh + gb);
            cpasync16(s0 + 24576 + sw, Bl + gb);
        }
        cp_commit();
    };

    load_chunk(0, 0);
    load_chunk(1, 1);

    for (int c = 0; c < NCH; c++) {
        if (c + 2 < NCH) {
            load_chunk(c + 2, (c + 2) % 3);
            cp_wait<2>();
        } else if (c + 1 < NCH) {
            cp_wait<1>();
        } else {
            cp_wait<0>();
        }
        __syncthreads();

        const uint32_t s0 = tb + (c % 3) * 32768;
        const uint32_t sAh = s0, sAl = s0 + 8192, sBh = s0 + 16384, sBl = s0 + 24576;

#pragma unroll
        for (int ks = 0; ks < 2; ks++) {
            const int kk = ks * 16 + koff;
            uint32_t ahf[2][4], alf[2][4];
#pragma unroll
            for (int mf = 0; mf < 2; mf++) {
                const uint32_t sw = sw64((uint32_t)(wm + mf * 16 + frow) * 64 + kk * 2);
                ldsm4(ahf[mf], sAh + sw);
                ldsm4(alf[mf], sAl + sw);
            }
#pragma unroll
            for (int np = 0; np < 4; np++) {
                const uint32_t sw = sw64((uint32_t)(wn + np * 16 + frow) * 64 + kk * 2);
                uint32_t bhf[4], blf[4];
                ldsm4(bhf, sBh + sw);
                ldsm4(blf, sBl + sw);
#pragma unroll
                for (int mf = 0; mf < 2; mf++) {
                    mma16816(acc[mf][np * 2 + 0], ahf[mf], bhf[0], bhf[2]);
                    mma16816(acc[mf][np * 2 + 0], ahf[mf], blf[0], blf[2]);
                    mma16816(acc[mf][np * 2 + 0], alf[mf], bhf[0], bhf[2]);
                    mma16816(acc[mf][np * 2 + 1], ahf[mf], bhf[1], bhf[3]);
                    mma16816(acc[mf][np * 2 + 1], ahf[mf], blf[1], blf[3]);
                    mma16816(acc[mf][np * 2 + 1], alf[mf], bhf[1], bhf[3]);
                }
            }
        }
        __syncthreads();
    }

    __nv_bfloat16* Ch = nullptr;
    __nv_bfloat16* Cl = nullptr;
    bool rope = false;
    if (MODE == 3) {
        Ch = (blockIdx.z == 0) ? Qh : (blockIdx.z == 1) ? Kh : Vh;
        Cl = (blockIdx.z == 0) ? Ql : (blockIdx.z == 1) ? Kl : Vl;
        rope = (blockIdx.z < 2);
    }

    const int r_lane = l >> 2;
    const int c_lane = (l & 3) * 2;
#pragma unroll
    for (int mf = 0; mf < 2; mf++) {
#pragma unroll
        for (int half = 0; half < 2; half++) {
            const int mrow = bm + wm + mf * 16 + r_lane + half * 8;
            const int b = mrow >> 11;            // SEQ = 2048
            const int s = mrow & (SEQ - 1);
#pragma unroll
            for (int nf = 0; nf < 8; nf++) {
                float e = acc[mf][nf][half * 2 + 0];
                float o = acc[mf][nf][half * 2 + 1];
                const int col = bn + wn + nf * 8 + c_lane;   // even
                if (MODE == 0) {
                    float2 v; v.x = e; v.y = o;
                    *(float2*)(C + (size_t)mrow * DM + col) = v;
                } else {
                    const int h = col >> 6;
                    const int d0 = col & 63;
                    if (rope) {
                        const int p = d0 >> 1;
                        const float cs = g_cos[s * 32 + p];
                        const float sn = g_sin[s * 32 + p];
                        const float re = e * cs - o * sn;
                        const float ro = e * sn + o * cs;
                        e = re; o = ro;
                    }
                    const size_t idx = (((size_t)b * NH + h) * SEQ + s) * HD + d0;
                    uint32_t hi, lo;
                    split_pack(e, o, hi, lo);
                    *(uint32_t*)(Ch + idx) = hi;
                    *(uint32_t*)(Cl + idx) = lo;
                }
            }
        }
    }
}

// ---------------- HMMA flash attention (split-bf16, causal, cp.async pipelined) ----
// grid (SEQ/64, BATCH*NH), 128 threads = 4 warps x 16 query rows.
// Longest blocks (largest qb) scheduled first via reversed mapping.
__global__ void __launch_bounds__(128) attn_hmma_kernel(__nv_bfloat16* __restrict__ Oh,
                                                        __nv_bfloat16* __restrict__ Ol)
{
    const int qb = (int)gridDim.x - 1 - (int)blockIdx.x;   // longest-first scheduling
    const int bh = blockIdx.y;
    const int b  = bh >> 4;
    const int h  = bh & 15;
    const size_t base = (size_t)bh * SEQ * HD;

    extern __shared__ char smem[];
    const uint32_t tb  = (smem_u32(smem) + 127) & ~127u;
    const uint32_t sQh = tb;
    const uint32_t sQl = tb + 8192;
    const uint32_t kvb = tb + 16384;   // stage s: kvb + s*32768; Kh,Kl,Vh,Vl at +0,8192,16384,24576

    const int tid = threadIdx.x;
    const int wid = tid >> 5;
    const int l   = tid & 31;
    const int wm  = wid * 16;
    const int frow = (l & 7) + ((l >> 3) & 1) * 8;
    const int koff = ((l >> 4) & 1) * 8;
    const int r  = l >> 2;
    const int cj = (l & 3) * 2;

    auto load_kv = [&](int jb, int st) {
        const uint32_t s0 = kvb + st * 32768;
#pragma unroll
        for (int i = 0; i < 4; i++) {
            const int id = tid + i * 128;
            const int row = id >> 3;
            const int ch = id & 7;
            const uint32_t sw = sw128((uint32_t)row * 128 + ch * 16);
            const size_t g = base + (size_t)(jb * 64 + row) * HD + ch * 8;
            cpasync16(s0 + sw,         g_Kh + g);
            cpasync16(s0 + 8192 + sw,  g_Kl + g);
            cpasync16(s0 + 16384 + sw, g_Vh + g);
            cpasync16(s0 + 24576 + sw, g_Vl + g);
        }
        cp_commit();
    };

    load_kv(0, 0);

    // load Q tile (64 x 64 bf16, hi+lo) swizzled
#pragma unroll
    for (int i = 0; i < 4; i++) {
        const int id = tid + i * 128;
        const int row = id >> 3;
        const int ch = id & 7;
        const uint32_t sw = sw128((uint32_t)row * 128 + ch * 16);
        const size_t g = base + (size_t)(qb * 64 + row) * HD + ch * 8;
        sts128(sQh + sw, *(const uint4*)(g_Qh + g));
        sts128(sQl + sw, *(const uint4*)(g_Ql + g));
    }
    __syncthreads();

    // preload Q fragments (16 rows x 64 k)
    uint32_t qh[4][4], ql[4][4];
#pragma unroll
    for (int ks = 0; ks < 4; ks++) {
        const uint32_t sw = sw128((uint32_t)(wm + frow) * 128 + (ks * 16 + koff) * 2);
        ldsm4(qh[ks], sQh + sw);
        ldsm4(ql[ks], sQl + sw);
    }

    float m0 = -1e30f, m1 = -1e30f, l0 = 0.0f, l1 = 0.0f;
    float o[8][4];
#pragma unroll
    for (int nf = 0; nf < 8; nf++)
#pragma unroll
        for (int q = 0; q < 4; q++) o[nf][q] = 0.0f;

    for (int jb = 0; jb <= qb; jb++) {
        if (jb + 1 <= qb) {
            load_kv(jb + 1, (jb + 1) & 1);
            cp_wait<1>();
        } else {
            cp_wait<0>();
        }
        __syncthreads();

        const uint32_t s0 = kvb + (jb & 1) * 32768;
        const uint32_t sKh = s0, sKl = s0 + 8192, sVh = s0 + 16384, sVl = s0 + 24576;

        // S = Q @ K^T (split 3-MMA), 16x64 per warp
        float sv[8][4];
#pragma unroll
        for (int nf = 0; nf < 8; nf++)
#pragma unroll
            for (int q = 0; q < 4; q++) sv[nf][q] = 0.0f;

#pragma unroll
        for (int np = 0; np < 4; np++) {
#pragma unroll
            for (int ks = 0; ks < 4; ks++) {
                const uint32_t sw = sw128((uint32_t)(np * 16 + frow) * 128 + (ks * 16 + koff) * 2);
                uint32_t khf[4], klf[4];
                ldsm4(khf, sKh + sw);
                ldsm4(klf, sKl + sw);
                mma16816(sv[np * 2 + 0], qh[ks], khf[0], khf[2]);
                mma16816(sv[np * 2 + 0], qh[ks], klf[0], klf[2]);
                mma16816(sv[np * 2 + 0], ql[ks], khf[0], khf[2]);
                mma16816(sv[np * 2 + 1], qh[ks], khf[1], khf[3]);
                mma16816(sv[np * 2 + 1], qh[ks], klf[1], klf[3]);
                mma16816(sv[np * 2 + 1], ql[ks], khf[1], khf[3]);
            }
        }

        // scale + causal mask (diagonal tile only)
#pragma unroll
        for (int nf = 0; nf < 8; nf++)
#pragma unroll
            for (int q = 0; q < 4; q++) sv[nf][q] *= 0.125f;

        if (jb == qb) {
#pragma unroll
            for (int nf = 0; nf < 8; nf++) {
                const int k0 = nf * 8 + cj;
                const int q0 = wm + r;
                if (k0     > q0)     sv[nf][0] = -1e30f;
                if (k0 + 1 > q0)     sv[nf][1] = -1e30f;
                if (k0     > q0 + 8) sv[nf][2] = -1e30f;
                if (k0 + 1 > q0 + 8) sv[nf][3] = -1e30f;
            }
        }

        // online softmax, rows r (regs 0,1) and r+8 (regs 2,3)
        float mt0 = -1e30f, mt1 = -1e30f;
#pragma unroll
        for (int nf = 0; nf < 8; nf++) {
            mt0 = fmaxf(mt0, fmaxf(sv[nf][0], sv[nf][1]));
            mt1 = fmaxf(mt1, fmaxf(sv[nf][2], sv[nf][3]));
        }
        mt0 = fmaxf(mt0, __shfl_xor_sync(0xffffffffu, mt0, 1));
        mt0 = fmaxf(mt0, __shfl_xor_sync(0xffffffffu, mt0, 2));
        mt1 = fmaxf(mt1, __shfl_xor_sync(0xffffffffu, mt1, 1));
        mt1 = fmaxf(mt1, __shfl_xor_sync(0xffffffffu, mt1, 2));
        const float mn0 = fmaxf(m0, mt0);
        const float mn1 = fmaxf(m1, mt1);

        float ls0 = 0.0f, ls1 = 0.0f;
#pragma unroll
        for (int nf = 0; nf < 8; nf++) {
            sv[nf][0] = __expf(sv[nf][0] - mn0);
            sv[nf][1] = __expf(sv[nf][1] - mn0);
            sv[nf][2] = __expf(sv[nf][2] - mn1);
            sv[nf][3] = __expf(sv[nf][3] - mn1);
            ls0 += sv[nf][0] + sv[nf][1];
            ls1 += sv[nf][2] + sv[nf][3];
        }
        ls0 += __shfl_xor_sync(0xffffffffu, ls0, 1);
        ls0 += __shfl_xor_sync(0xffffffffu, ls0, 2);
        ls1 += __shfl_xor_sync(0xffffffffu, ls1, 1);
        ls1 += __shfl_xor_sync(0xffffffffu, ls1, 2);

        const float a0 = __expf(m0 - mn0);
        const float a1 = __expf(m1 - mn1);
        l0 = l0 * a0 + ls0;
        l1 = l1 * a1 + ls1;
        m0 = mn0; m1 = mn1;
#pragma unroll
        for (int nf = 0; nf < 8; nf++) {
            o[nf][0] *= a0; o[nf][1] *= a0;
            o[nf][2] *= a1; o[nf][3] *= a1;
        }

        // O += P @ V (split 3-MMA), P fragments straight from accumulators
#pragma unroll
        for (int kp = 0; kp < 4; kp++) {
            uint32_t Ph[4], Pl[4];
            split_pack(sv[2 * kp][0],     sv[2 * kp][1],     Ph[0], Pl[0]);
            split_pack(sv[2 * kp][2],     sv[2 * kp][3],     Ph[1], Pl[1]);
            split_pack(sv[2 * kp + 1][0], sv[2 * kp + 1][1], Ph[2], Pl[2]);
            split_pack(sv[2 * kp + 1][2], sv[2 * kp + 1][3], Ph[3], Pl[3]);
#pragma unroll
            for (int hp = 0; hp < 4; hp++) {
                const uint32_t sw = sw128((uint32_t)(kp * 16 + frow) * 128 + (hp * 16 + koff) * 2);
                uint32_t vhf[4], vlf[4];
                ldsm4t(vhf, sVh + sw);
                ldsm4t(vlf, sVl + sw);
                mma16816(o[hp * 2 + 0], Ph, vhf[0], vhf[1]);
                mma16816(o[hp * 2 + 0], Ph, vlf[0], vlf[1]);
                mma16816(o[hp * 2 + 0], Pl, vhf[0], vhf[1]);
                mma16816(o[hp * 2 + 1], Ph, vhf[2], vhf[3]);
                mma16816(o[hp * 2 + 1], Ph, vlf[2], vlf[3]);
                mma16816(o[hp * 2 + 1], Pl, vhf[2], vhf[3]);
            }
        }
        __syncthreads();
    }

    // epilogue: normalize, split-bf16 scatter to concat [b][s][d]
    const float inv0 = 1.0f / l0;
    const float inv1 = 1.0f / l1;
    const int q0 = qb * 64 + wm + r;
    const int q1 = q0 + 8;
#pragma unroll
    for (int nf = 0; nf < 8; nf++) {
        const int col = h * HD + nf * 8 + cj;
        uint32_t hi, lo;
        split_pack(o[nf][0] * inv0, o[nf][1] * inv0, hi, lo);
        const size_t i0 = ((size_t)b * SEQ + q0) * DM + col;
        *(uint32_t*)(Oh + i0) = hi;
        *(uint32_t*)(Ol + i0) = lo;
        split_pack(o[nf][2] * inv1, o[nf][3] * inv1, hi, lo);
        const size_t i1 = ((size_t)b * SEQ + q1) * DM + col;
        *(uint32_t*)(Oh + i1) = hi;
        *(uint32_t*)(Ol + i1) = lo;
    }
}

// ---------------- launch ----------------
extern "C" void kernel_launch(void* const* d_in, const int* in_sizes, int n_in,
                              void* d_out, int out_size)
{
    const float* x  = (const float*)d_in[0];
    const float* Wq = (const float*)d_in[1];
    const float* Wk = (const float*)d_in[2];
    const float* Wv = (const float*)d_in[3];
    const float* Wo = (const float*)d_in[4];
    float* out = (float*)d_out;

    __nv_bfloat16 *pAh, *pAl, *pWh, *pWl, *pQh, *pQl, *pKh, *pKl, *pVh, *pVl;
    cudaGetSymbolAddress((void**)&pAh, g_Ah);
    cudaGetSymbolAddress((void**)&pAl, g_Al);
    cudaGetSymbolAddress((void**)&pWh, g_Wh);
    cudaGetSymbolAddress((void**)&pWl, g_Wl);
    cudaGetSymbolAddress((void**)&pQh, g_Qh);
    cudaGetSymbolAddress((void**)&pQl, g_Ql);
    cudaGetSymbolAddress((void**)&pKh, g_Kh);
    cudaGetSymbolAddress((void**)&pKl, g_Kl);
    cudaGetSymbolAddress((void**)&pVh, g_Vh);
    cudaGetSymbolAddress((void**)&pVl, g_Vl);

    const int GSMEM = 3 * 32768 + 256;          // 3-stage, K-chunk 32 -> 2 CTAs/SM
    cudaFuncSetAttribute(tgemm_kernel<0>, cudaFuncAttributeMaxDynamicSharedMemorySize, GSMEM);
    cudaFuncSetAttribute(tgemm_kernel<3>, cudaFuncAttributeMaxDynamicSharedMemorySize, GSMEM);

    rope_table_kernel<<<(SEQ * 32 + 255) / 256, 256>>>();

    const int nx4 = BATCH * SEQ * DM / 4;
    const int nw4 = DM * DM / 4;
    split_kernel<<<(nx4 + 255) / 256, 256>>>(x, pAh, pAl, nx4);
    split4_kernel<<<(4 * nw4 + 255) / 256, 256>>>(Wq, Wk, Wv, Wo, pWh, pWl, nw4);

    // fused QKV projections: grid.z selects weight + output
    dim3 qkvgrid(DM / 128, BATCH * SEQ / 128, 3);   // (8, 32, 3)
    tgemm_kernel<3><<<qkvgrid, 256, GSMEM>>>(pAh, pAl, pWh, pWl,
                                             nullptr, pQh, pQl, pKh, pKl, pVh, pVl);

    const int ASMEM = 16384 + 2 * 32768 + 256;  // Q + double-buffered KV
    cudaFuncSetAttribute(attn_hmma_kernel, cudaFuncAttributeMaxDynamicSharedMemorySize, ASMEM);
    attn_hmma_kernel<<<dim3(SEQ / 64, BATCH * NH), 128, ASMEM>>>(pAh, pAl);

    dim3 ogrid(DM / 128, BATCH * SEQ / 128);
    tgemm_kernel<0><<<ogrid, 256, GSMEM>>>(pAh, pAl, pWh + 3 * (size_t)DM * DM, pWl + 3 * (size_t)DM * DM,
                                           out, nullptr, nullptr, nullptr, nullptr, nullptr, nullptr);
}